// round 5
// baseline (speedup 1.0000x reference)
#include <cuda_runtime.h>
#include <cuda_bf16.h>
#include <cstdint>

#define BB 4
#define TT 2048
#define CC 1024
#define HH 16
#define DD 64
#define BT_ (BB*TT)      // 8192
#define N3C (3*CC)       // 3072
#define KK  1024         // inner dim (per pass)

// ---------------------------------------------------------------------------
// Device scratch (allocation-free rule: __device__ globals)
// ---------------------------------------------------------------------------
__device__ float g_q[BB*HH*TT*DD];          // [B,H,T,D] fp32
__device__ float g_k[BB*HH*TT*DD];
__device__ float g_v[BB*HH*TT*DD];

__device__ __nv_bfloat16 g_xh[BT_*CC];      // X split hi [M,K]
__device__ __nv_bfloat16 g_xl[BT_*CC];      // X split lo
__device__ __nv_bfloat16 g_wh[N3C*CC];      // qkv_w^T split hi [N,K]
__device__ __nv_bfloat16 g_wl[N3C*CC];
__device__ __nv_bfloat16 g_ph[CC*CC];       // proj_w^T split hi [N,K]
__device__ __nv_bfloat16 g_pl[CC*CC];
__device__ __nv_bfloat16 g_ah[BT_*CC];      // attention out split hi [M,K]
__device__ __nv_bfloat16 g_al[BT_*CC];

// ---------------------------------------------------------------------------
// Helpers (plain sm_103-safe PTX only: ldmatrix + mma.sync, no tcgen05/TMA)
// ---------------------------------------------------------------------------
__device__ __forceinline__ uint32_t smem_u32(const void* p) {
    uint32_t a;
    asm("{ .reg .u64 t; cvta.to.shared.u64 t, %1; cvt.u32.u64 %0, t; }"
        : "=r"(a) : "l"(p));
    return a;
}
__device__ __forceinline__ void ldmatrix_x4(uint32_t* r, uint32_t addr) {
    asm volatile("ldmatrix.sync.aligned.m8n8.x4.shared.b16 {%0,%1,%2,%3}, [%4];"
                 : "=r"(r[0]), "=r"(r[1]), "=r"(r[2]), "=r"(r[3]) : "r"(addr));
}
__device__ __forceinline__ void ldmatrix_x2(uint32_t* r, uint32_t addr) {
    asm volatile("ldmatrix.sync.aligned.m8n8.x2.shared.b16 {%0,%1}, [%2];"
                 : "=r"(r[0]), "=r"(r[1]) : "r"(addr));
}
__device__ __forceinline__ void mma_bf16(float* d, const uint32_t* a, const uint32_t* b) {
    asm volatile(
        "mma.sync.aligned.m16n8k16.row.col.f32.bf16.bf16.f32 "
        "{%0,%1,%2,%3}, {%4,%5,%6,%7}, {%8,%9}, {%0,%1,%2,%3};"
        : "+f"(d[0]), "+f"(d[1]), "+f"(d[2]), "+f"(d[3])
        : "r"(a[0]), "r"(a[1]), "r"(a[2]), "r"(a[3]), "r"(b[0]), "r"(b[1]));
}

// ---------------------------------------------------------------------------
// Split helpers
// ---------------------------------------------------------------------------
__global__ void split_f32_kernel(const float* __restrict__ in,
                                 __nv_bfloat16* __restrict__ hi,
                                 __nv_bfloat16* __restrict__ lo, int n4)
{
    int i = blockIdx.x * blockDim.x + threadIdx.x;
    if (i >= n4) return;
    float4 v = ((const float4*)in)[i];
    __nv_bfloat16 h0 = __float2bfloat16(v.x);
    __nv_bfloat16 h1 = __float2bfloat16(v.y);
    __nv_bfloat16 h2 = __float2bfloat16(v.z);
    __nv_bfloat16 h3 = __float2bfloat16(v.w);
    __nv_bfloat162* hp = (__nv_bfloat162*)(hi + i*4);
    __nv_bfloat162* lp = (__nv_bfloat162*)(lo + i*4);
    hp[0] = __nv_bfloat162(h0, h1);
    hp[1] = __nv_bfloat162(h2, h3);
    lp[0] = __nv_bfloat162(__float2bfloat16(v.x - __bfloat162float(h0)),
                           __float2bfloat16(v.y - __bfloat162float(h1)));
    lp[1] = __nv_bfloat162(__float2bfloat16(v.z - __bfloat162float(h2)),
                           __float2bfloat16(v.w - __bfloat162float(h3)));
}

// in [R, C] f32 -> out [C, R] bf16 hi/lo  (transpose + split)
__global__ void transpose_split_kernel(const float* __restrict__ in,
                                       __nv_bfloat16* __restrict__ hi,
                                       __nv_bfloat16* __restrict__ lo,
                                       int R, int C)
{
    __shared__ float s[32][33];
    int c0 = blockIdx.x * 32, r0 = blockIdx.y * 32;
    int tx = threadIdx.x, ty = threadIdx.y;   // (32, 8)
    #pragma unroll
    for (int i = ty; i < 32; i += 8)
        s[i][tx] = in[(size_t)(r0 + i) * C + c0 + tx];
    __syncthreads();
    #pragma unroll
    for (int i = ty; i < 32; i += 8) {
        float v = s[tx][i];                   // = in[r0+tx][c0+i]
        __nv_bfloat16 h = __float2bfloat16(v);
        size_t o = (size_t)(c0 + i) * R + r0 + tx;
        hi[o] = h;
        lo[o] = __float2bfloat16(v - __bfloat162float(h));
    }
}

// ---------------------------------------------------------------------------
// Warp-MMA bf16 GEMM with error-compensated split:
//   C = Ah*Bh + Al*Bh + Ah*Bl  (effective K' = 3*1024, residual ~2^-18)
// A [M,K] row-major bf16, B [N,K] row-major bf16 (i.e. W^T), fp32 accum.
// Block 128x128, 8 warps (2x4 -> 64x32 warp tiles), K-chunk 32, double buffer.
// MODE 0: bias + scatter to g_q/g_k/g_v [B,H,T,D].  MODE 1: bias + out [M,C].
// ---------------------------------------------------------------------------
#define GP     40            // smem pitch in bf16 elements (80B, conflict-free)
#define CHUNKS 96            // 3 passes * 32 chunks of K=32

template<int MODE>
__global__ __launch_bounds__(256, 1)
void mma_gemm(const __nv_bfloat16* __restrict__ Ah, const __nv_bfloat16* __restrict__ Al,
              const __nv_bfloat16* __restrict__ Bh, const __nv_bfloat16* __restrict__ Bl,
              const float* __restrict__ bias, float* __restrict__ out)
{
    __shared__ __align__(16) __nv_bfloat16 As[2][128*GP];
    __shared__ __align__(16) __nv_bfloat16 Bs[2][128*GP];

    const int tid  = threadIdx.x;
    const int lane = tid & 31, wid = tid >> 5;
    const int wr = wid >> 2, wc = wid & 3;          // warp tile: rows wr*64, cols wc*32
    const int bM = blockIdx.y * 128, bN = blockIdx.x * 128;

    // global staging coords: thread -> (row, 16-col half)
    const int gRow = tid >> 1;
    const int gC   = (tid & 1) * 16;

    const uint32_t asb = smem_u32(As[0]);
    const uint32_t bsb = smem_u32(Bs[0]);
    const uint32_t bufB = 128 * GP * 2;             // bytes per buffer

    // ldmatrix per-lane byte offsets within a buffer
    const uint32_t aOff = (uint32_t)(wr*64 + (lane & 15)) * (GP*2) + ((lane >> 4) << 4);
    const uint32_t bOff = (uint32_t)(wc*32 + (lane & 15 & 7)) * (GP*2) + (((lane >> 3) & 1) << 4);

    float acc[4][4][4];
    #pragma unroll
    for (int mt = 0; mt < 4; mt++)
        #pragma unroll
        for (int nt = 0; nt < 4; nt++)
            #pragma unroll
            for (int r = 0; r < 4; r++) acc[mt][nt][r] = 0.f;

    // preload chunk 0 (pass 0: Ah, Bh)
    {
        const uint4* ag = (const uint4*)(Ah + (size_t)(bM + gRow) * KK + gC);
        const uint4* bg = (const uint4*)(Bh + (size_t)(bN + gRow) * KK + gC);
        uint4 a0 = ag[0], a1 = ag[1], b0 = bg[0], b1 = bg[1];
        char* ad = (char*)As[0] + gRow*(GP*2) + gC*2;
        char* bd = (char*)Bs[0] + gRow*(GP*2) + gC*2;
        *(uint4*)ad = a0; *(uint4*)(ad + 16) = a1;
        *(uint4*)bd = b0; *(uint4*)(bd + 16) = b1;
    }
    __syncthreads();

    for (int c = 0; c < CHUNKS; c++) {
        const int cur = c & 1;
        uint4 pa0, pa1, pb0, pb1;
        if (c + 1 < CHUNKS) {
            const int g = c + 1;
            const int pass = g >> 5;                 // 0:(Ah,Bh) 1:(Al,Bh) 2:(Ah,Bl)
            const int k0 = (g & 31) * 32;
            const __nv_bfloat16* Ap = (pass == 1) ? Al : Ah;
            const __nv_bfloat16* Bp = (pass == 2) ? Bl : Bh;
            const uint4* ag = (const uint4*)(Ap + (size_t)(bM + gRow) * KK + k0 + gC);
            const uint4* bg = (const uint4*)(Bp + (size_t)(bN + gRow) * KK + k0 + gC);
            pa0 = ag[0]; pa1 = ag[1]; pb0 = bg[0]; pb1 = bg[1];
        }

        const uint32_t aBase = asb + cur * bufB + aOff;
        const uint32_t bBase = bsb + cur * bufB + bOff;
        #pragma unroll
        for (int ks = 0; ks < 2; ks++) {
            uint32_t af[4][4], bf[4][2];
            #pragma unroll
            for (int mt = 0; mt < 4; mt++)
                ldmatrix_x4(af[mt], aBase + (uint32_t)(mt*16*(GP*2)) + ks*32);
            #pragma unroll
            for (int nt = 0; nt < 4; nt++)
                ldmatrix_x2(bf[nt], bBase + (uint32_t)(nt*8*(GP*2)) + ks*32);
            #pragma unroll
            for (int mt = 0; mt < 4; mt++)
                #pragma unroll
                for (int nt = 0; nt < 4; nt++)
                    mma_bf16(acc[mt][nt], af[mt], bf[nt]);
        }

        if (c + 1 < CHUNKS) {
            const int nb = cur ^ 1;
            char* ad = (char*)As[nb] + gRow*(GP*2) + gC*2;
            char* bd = (char*)Bs[nb] + gRow*(GP*2) + gC*2;
            *(uint4*)ad = pa0; *(uint4*)(ad + 16) = pa1;
            *(uint4*)bd = pb0; *(uint4*)(bd + 16) = pb1;
        }
        __syncthreads();
    }

    // epilogue: accum layout m16n8 -> rows lane/4 (+8), cols 2*(lane&3)(+1)
    const int mrow0 = bM + wr*64 + (lane >> 2);
    #pragma unroll
    for (int nt = 0; nt < 4; nt++) {
        const int gcol = bN + wc*32 + nt*8 + (lane & 3)*2;
        const float2 bz = *(const float2*)(bias + gcol);
        float* dstbase;
        int h = 0, d0 = 0;
        if (MODE == 0) {
            const int which = gcol >> 10;
            const int rem = gcol & 1023;
            h = rem >> 6; d0 = rem & 63;
            dstbase = (which == 0) ? g_q : (which == 1 ? g_k : g_v);
        } else {
            dstbase = out;
        }
        #pragma unroll
        for (int mt = 0; mt < 4; mt++) {
            #pragma unroll
            for (int h2 = 0; h2 < 2; h2++) {
                const int row = mrow0 + mt*16 + h2*8;
                float2 v;
                v.x = acc[mt][nt][h2*2 + 0] + bz.x;
                v.y = acc[mt][nt][h2*2 + 1] + bz.y;
                if (MODE == 0) {
                    const int b_ = row >> 11, t_ = row & (TT - 1);
                    *(float2*)(dstbase + ((size_t)(b_*HH + h)*TT + t_)*DD + d0) = v;
                } else {
                    *(float2*)(dstbase + (size_t)row * CC + gcol) = v;
                }
            }
        }
    }
}

// ---------------------------------------------------------------------------
// Flash attention (fp32 SIMT) — epilogue writes bf16 hi/lo for proj GEMM
// ---------------------------------------------------------------------------
#define ATT_SMEM ((64*64 + 64*65 + 64*64) * 4)

__global__ __launch_bounds__(128, 4)
void attn_kernel()
{
    extern __shared__ float sm[];
    float* Qs  = sm;
    float* KVs = sm + 64*64;
    float* Ps  = sm + 64*64 + 64*65;

    const int tid = threadIdx.x;
    const int tx = tid & 15, ty = tid >> 4;
    const int qb = blockIdx.x;
    const int bh = blockIdx.y;
    const int b_ = bh >> 4, h = bh & 15;

    const float* Qg = g_q + ((size_t)bh * TT + qb*64) * DD;
    const float* Kg = g_k + (size_t)bh * TT * DD;
    const float* Vg = g_v + (size_t)bh * TT * DD;

    #pragma unroll
    for (int p = 0; p < 8; p++) {
        int idx = (p*128 + tid) * 4;
        *(float4*)(Qs + idx) = *(const float4*)(Qg + idx);
    }

    float m_i[8], l_i[8], o[8][4];
    #pragma unroll
    for (int i = 0; i < 8; i++) {
        m_i[i] = __int_as_float(0xff800000);
        l_i[i] = 0.f;
        #pragma unroll
        for (int j = 0; j < 4; j++) o[i][j] = 0.f;
    }

    const float scale = 0.125f;

    for (int kt = 0; kt < TT/64; kt++) {
        __syncthreads();
        {
            const float* src = Kg + (size_t)kt * 64 * DD;
            #pragma unroll
            for (int p = 0; p < 8; p++) {
                int idx = (p*128 + tid) * 4;
                int c = idx >> 6, k0 = idx & 63;
                float4 v4 = *(const float4*)(src + idx);
                float* d = KVs + c*65 + k0;
                d[0] = v4.x; d[1] = v4.y; d[2] = v4.z; d[3] = v4.w;
            }
        }
        __syncthreads();

        float s[8][4];
        #pragma unroll
        for (int i = 0; i < 8; i++)
            #pragma unroll
            for (int j = 0; j < 4; j++) s[i][j] = 0.f;

        #pragma unroll 4
        for (int k = 0; k < 64; k++) {
            float q[8], kk[4];
            #pragma unroll
            for (int i = 0; i < 8; i++) q[i] = Qs[(ty*8 + i)*64 + k];
            #pragma unroll
            for (int j = 0; j < 4; j++) kk[j] = KVs[(tx + 16*j)*65 + k];
            #pragma unroll
            for (int i = 0; i < 8; i++)
                #pragma unroll
                for (int j = 0; j < 4; j++)
                    s[i][j] += q[i] * kk[j];
        }

        #pragma unroll
        for (int i = 0; i < 8; i++) {
            #pragma unroll
            for (int j = 0; j < 4; j++) s[i][j] *= scale;
            float mx = fmaxf(fmaxf(s[i][0], s[i][1]), fmaxf(s[i][2], s[i][3]));
            mx = fmaxf(mx, __shfl_xor_sync(0xffffffffu, mx, 8));
            mx = fmaxf(mx, __shfl_xor_sync(0xffffffffu, mx, 4));
            mx = fmaxf(mx, __shfl_xor_sync(0xffffffffu, mx, 2));
            mx = fmaxf(mx, __shfl_xor_sync(0xffffffffu, mx, 1));
            float mnew  = fmaxf(m_i[i], mx);
            float alpha = __expf(m_i[i] - mnew);
            m_i[i] = mnew;
            float lsum = 0.f;
            #pragma unroll
            for (int j = 0; j < 4; j++) {
                float p = __expf(s[i][j] - mnew);
                Ps[(ty*8 + i)*64 + tx + 16*j] = p;
                lsum += p;
            }
            lsum += __shfl_xor_sync(0xffffffffu, lsum, 8);
            lsum += __shfl_xor_sync(0xffffffffu, lsum, 4);
            lsum += __shfl_xor_sync(0xffffffffu, lsum, 2);
            lsum += __shfl_xor_sync(0xffffffffu, lsum, 1);
            l_i[i] = l_i[i] * alpha + lsum;
            #pragma unroll
            for (int j = 0; j < 4; j++) o[i][j] *= alpha;
        }
        __syncthreads();

        {
            const float* src = Vg + (size_t)kt * 64 * DD;
            #pragma unroll
            for (int p = 0; p < 8; p++) {
                int idx = (p*128 + tid) * 4;
                int c = idx >> 6, k0 = idx & 63;
                float4 v4 = *(const float4*)(src + idx);
                float* d = KVs + c*65 + k0;
                d[0] = v4.x; d[1] = v4.y; d[2] = v4.z; d[3] = v4.w;
            }
        }
        __syncthreads();

        #pragma unroll 4
        for (int c = 0; c < 64; c++) {
            float pr[8], vv[4];
            #pragma unroll
            for (int j = 0; j < 4; j++) vv[j] = KVs[c*65 + tx + 16*j];
            #pragma unroll
            for (int i = 0; i < 8; i++) pr[i] = Ps[(ty*8 + i)*64 + c];
            #pragma unroll
            for (int i = 0; i < 8; i++)
                #pragma unroll
                for (int j = 0; j < 4; j++)
                    o[i][j] += pr[i] * vv[j];
        }
    }

    // Epilogue: normalize, split to bf16 hi/lo for the warp-MMA proj GEMM
    #pragma unroll
    for (int i = 0; i < 8; i++) {
        float inv = 1.f / l_i[i];
        int t_ = qb*64 + ty*8 + i;
        size_t base = ((size_t)b_ * TT + t_) * CC + h*64;
        #pragma unroll
        for (int j = 0; j < 4; j++) {
            float val = o[i][j] * inv;
            __nv_bfloat16 hbf = __float2bfloat16(val);
            size_t idx = base + tx + 16*j;
            g_ah[idx] = hbf;
            g_al[idx] = __float2bfloat16(val - __bfloat162float(hbf));
        }
    }
}

// ---------------------------------------------------------------------------
extern "C" void kernel_launch(void* const* d_in, const int* in_sizes, int n_in,
                              void* d_out, int out_size)
{
    const float* x      = (const float*)d_in[0];
    const float* qkv_w  = (const float*)d_in[1];
    const float* qkv_b  = (const float*)d_in[2];
    const float* proj_w = (const float*)d_in[3];
    const float* proj_b = (const float*)d_in[4];
    float* out = (float*)d_out;
    (void)in_sizes; (void)n_in; (void)out_size;

    cudaFuncSetAttribute(attn_kernel,
                         cudaFuncAttributeMaxDynamicSharedMemorySize, ATT_SMEM);

    __nv_bfloat16 *xh, *xl, *wh, *wl, *ph_, *pl_, *ah, *al;
    cudaGetSymbolAddress((void**)&xh, g_xh);
    cudaGetSymbolAddress((void**)&xl, g_xl);
    cudaGetSymbolAddress((void**)&wh, g_wh);
    cudaGetSymbolAddress((void**)&wl, g_wl);
    cudaGetSymbolAddress((void**)&ph_, g_ph);
    cudaGetSymbolAddress((void**)&pl_, g_pl);
    cudaGetSymbolAddress((void**)&ah, g_ah);
    cudaGetSymbolAddress((void**)&al, g_al);

    // 1) operand prep
    split_f32_kernel<<<(BT_*CC/4 + 255)/256, 256>>>(x, xh, xl, BT_*CC/4);
    transpose_split_kernel<<<dim3(N3C/32, CC/32), dim3(32, 8)>>>(qkv_w, wh, wl, CC, N3C);
    transpose_split_kernel<<<dim3(CC/32, CC/32), dim3(32, 8)>>>(proj_w, ph_, pl_, CC, CC);

    // 2) QKV GEMM (warp-MMA bf16, error-compensated) -> g_q/g_k/g_v
    mma_gemm<0><<<dim3(N3C/128, BT_/128), 256>>>(xh, xl, wh, wl, qkv_b, nullptr);

    // 3) attention (fp32) -> bf16 hi/lo
    attn_kernel<<<dim3(TT/64, BB*HH), 128, ATT_SMEM>>>();

    // 4) output projection (warp-MMA bf16) -> d_out
    mma_gemm<1><<<dim3(CC/128, BT_/128), 256>>>(ah, al, ph_, pl_, proj_b, out);
}

// round 6
// speedup vs baseline: 1.8945x; 1.8945x over previous
#include <cuda_runtime.h>
#include <cuda_bf16.h>
#include <cstdint>

#define BB 4
#define TT 2048
#define CC 1024
#define HH 16
#define DD 64
#define BT_ (BB*TT)      // 8192
#define N3C (3*CC)       // 3072
#define KK  1024         // inner dim (per pass)

// ---------------------------------------------------------------------------
// Device scratch (allocation-free rule: __device__ globals)
// ---------------------------------------------------------------------------
__device__ float g_q[BB*HH*TT*DD];          // [B,H,T,D] fp32
__device__ float g_k[BB*HH*TT*DD];
__device__ float g_v[BB*HH*TT*DD];

__device__ __nv_bfloat16 g_xh[BT_*CC];      // X split hi [M,K]
__device__ __nv_bfloat16 g_xl[BT_*CC];      // X split lo
__device__ __nv_bfloat16 g_wh[N3C*CC];      // qkv_w^T split hi [N,K]
__device__ __nv_bfloat16 g_wl[N3C*CC];
__device__ __nv_bfloat16 g_ph[CC*CC];       // proj_w^T split hi [N,K]
__device__ __nv_bfloat16 g_pl[CC*CC];
__device__ __nv_bfloat16 g_ah[BT_*CC];      // attention out split hi [M,K]
__device__ __nv_bfloat16 g_al[BT_*CC];

// ---------------------------------------------------------------------------
// Helpers (plain sm_103-safe PTX: ldmatrix + mma.sync + cp.async)
// ---------------------------------------------------------------------------
__device__ __forceinline__ uint32_t smem_u32(const void* p) {
    uint32_t a;
    asm("{ .reg .u64 t; cvta.to.shared.u64 t, %1; cvt.u32.u64 %0, t; }"
        : "=r"(a) : "l"(p));
    return a;
}
__device__ __forceinline__ void ldmatrix_x4(uint32_t* r, uint32_t addr) {
    asm volatile("ldmatrix.sync.aligned.m8n8.x4.shared.b16 {%0,%1,%2,%3}, [%4];"
                 : "=r"(r[0]), "=r"(r[1]), "=r"(r[2]), "=r"(r[3]) : "r"(addr));
}
__device__ __forceinline__ void ldmatrix_x2(uint32_t* r, uint32_t addr) {
    asm volatile("ldmatrix.sync.aligned.m8n8.x2.shared.b16 {%0,%1}, [%2];"
                 : "=r"(r[0]), "=r"(r[1]) : "r"(addr));
}
__device__ __forceinline__ void mma_bf16(float* d, const uint32_t* a, const uint32_t* b) {
    asm volatile(
        "mma.sync.aligned.m16n8k16.row.col.f32.bf16.bf16.f32 "
        "{%0,%1,%2,%3}, {%4,%5,%6,%7}, {%8,%9}, {%0,%1,%2,%3};"
        : "+f"(d[0]), "+f"(d[1]), "+f"(d[2]), "+f"(d[3])
        : "r"(a[0]), "r"(a[1]), "r"(a[2]), "r"(a[3]), "r"(b[0]), "r"(b[1]));
}
__device__ __forceinline__ void cp_async16(uint32_t s, const void* g) {
    asm volatile("cp.async.cg.shared.global [%0], [%1], 16;"
                 :: "r"(s), "l"(g) : "memory");
}
#define CP_COMMIT() asm volatile("cp.async.commit_group;" ::: "memory")
#define CP_WAIT2()  asm volatile("cp.async.wait_group 2;" ::: "memory")

// ---------------------------------------------------------------------------
// Split helpers
// ---------------------------------------------------------------------------
__global__ void split_f32_kernel(const float* __restrict__ in,
                                 __nv_bfloat16* __restrict__ hi,
                                 __nv_bfloat16* __restrict__ lo, int n4)
{
    int i = blockIdx.x * blockDim.x + threadIdx.x;
    if (i >= n4) return;
    float4 v = ((const float4*)in)[i];
    __nv_bfloat16 h0 = __float2bfloat16(v.x);
    __nv_bfloat16 h1 = __float2bfloat16(v.y);
    __nv_bfloat16 h2 = __float2bfloat16(v.z);
    __nv_bfloat16 h3 = __float2bfloat16(v.w);
    __nv_bfloat162* hp = (__nv_bfloat162*)(hi + i*4);
    __nv_bfloat162* lp = (__nv_bfloat162*)(lo + i*4);
    hp[0] = __nv_bfloat162(h0, h1);
    hp[1] = __nv_bfloat162(h2, h3);
    lp[0] = __nv_bfloat162(__float2bfloat16(v.x - __bfloat162float(h0)),
                           __float2bfloat16(v.y - __bfloat162float(h1)));
    lp[1] = __nv_bfloat162(__float2bfloat16(v.z - __bfloat162float(h2)),
                           __float2bfloat16(v.w - __bfloat162float(h3)));
}

// in [R, C] f32 -> out [C, R] bf16 hi/lo  (transpose + split)
__global__ void transpose_split_kernel(const float* __restrict__ in,
                                       __nv_bfloat16* __restrict__ hi,
                                       __nv_bfloat16* __restrict__ lo,
                                       int R, int C)
{
    __shared__ float s[32][33];
    int c0 = blockIdx.x * 32, r0 = blockIdx.y * 32;
    int tx = threadIdx.x, ty = threadIdx.y;   // (32, 8)
    #pragma unroll
    for (int i = ty; i < 32; i += 8)
        s[i][tx] = in[(size_t)(r0 + i) * C + c0 + tx];
    __syncthreads();
    #pragma unroll
    for (int i = ty; i < 32; i += 8) {
        float v = s[tx][i];                   // = in[r0+tx][c0+i]
        __nv_bfloat16 h = __float2bfloat16(v);
        size_t o = (size_t)(c0 + i) * R + r0 + tx;
        hi[o] = h;
        lo[o] = __float2bfloat16(v - __bfloat162float(h));
    }
}

// ---------------------------------------------------------------------------
// Warp-MMA bf16 GEMM, error-compensated split (C = AhBh + AlBh + AhBl).
// Block 128x128, 8 warps (64x32 warp tiles). K-chunk 64 (128B rows, SW128
// XOR swizzle), 4-stage cp.async pipeline (3 chunks of lead).
// MODE 0: bias + scatter to g_q/g_k/g_v.  MODE 1: bias + out [M,C].
// ---------------------------------------------------------------------------
#define KC       64
#define STAGES   4
#define OPBYTES  16384                 // one operand tile: 128 rows * 128 B
#define STG_B    (2*OPBYTES)           // A + B per stage
#define GSMEM    (STAGES*STG_B)        // 128 KB
#define CHUNKS   48                    // 3 passes * 16 chunks of K=64

template<int MODE>
__global__ __launch_bounds__(256, 1)
void mma_gemm(const __nv_bfloat16* __restrict__ Ah, const __nv_bfloat16* __restrict__ Al,
              const __nv_bfloat16* __restrict__ Bh, const __nv_bfloat16* __restrict__ Bl,
              const float* __restrict__ bias, float* __restrict__ out)
{
    extern __shared__ __align__(128) char gsm[];
    const uint32_t sbase = smem_u32(gsm);

    const int tid  = threadIdx.x;
    const int lane = tid & 31, wid = tid >> 5;
    const int wr = wid >> 2, wc = wid & 3;          // warp tile rows wr*64, cols wc*32
    const int bM = blockIdx.y * 128, bN = blockIdx.x * 128;

    // cp.async staging: thread -> row tid>>1, four 16B slots starting (tid&1)*4
    const int ldRow  = tid >> 1;
    const int ldS0   = (tid & 1) * 4;
    const uint32_t ldRowOff = (uint32_t)ldRow * 128;
    const uint32_t ldXor    = (uint32_t)(ldRow & 7);

    float acc[4][4][4];
    #pragma unroll
    for (int mt = 0; mt < 4; mt++)
        #pragma unroll
        for (int nt = 0; nt < 4; nt++)
            #pragma unroll
            for (int r = 0; r < 4; r++) acc[mt][nt][r] = 0.f;

    // ---- async load of one chunk (or empty commit past the end) ----
    auto issue_chunk = [&](int g) {
        if (g < CHUNKS) {
            const int pass = g >> 4;               // 0:(Ah,Bh) 1:(Al,Bh) 2:(Ah,Bl)
            const int k0 = (g & 15) * KC;
            const __nv_bfloat16* Ap = (pass == 1) ? Al : Ah;
            const __nv_bfloat16* Bp = (pass == 2) ? Bl : Bh;
            const uint32_t st = sbase + (uint32_t)(g & (STAGES-1)) * STG_B;
            const char* ga = (const char*)(Ap + (size_t)(bM + ldRow) * KK + k0) + ldS0*16;
            const char* gb = (const char*)(Bp + (size_t)(bN + ldRow) * KK + k0) + ldS0*16;
            #pragma unroll
            for (int i = 0; i < 4; i++) {
                const uint32_t sw = (uint32_t)(((ldS0 + i) ^ ldXor) << 4);
                cp_async16(st + ldRowOff + sw,           ga + i*16);
                cp_async16(st + OPBYTES + ldRowOff + sw, gb + i*16);
            }
        }
        CP_COMMIT();
    };

    issue_chunk(0);
    issue_chunk(1);
    issue_chunk(2);

    // per-lane ldmatrix address components (swizzle xor uses lane&7 only)
    const uint32_t aRowOff = (uint32_t)(wr*64 + (lane & 15)) * 128;
    const uint32_t bRowOff = (uint32_t)(wc*32 + (lane & 7)) * 128;
    const uint32_t ahalf = (uint32_t)(lane >> 4);
    const uint32_t bhalf = (uint32_t)((lane >> 3) & 1);
    const uint32_t lx    = (uint32_t)(lane & 7);

    for (int c = 0; c < CHUNKS; c++) {
        CP_WAIT2();
        __syncthreads();

        const uint32_t stA = sbase + (uint32_t)(c & (STAGES-1)) * STG_B;
        const uint32_t aB = stA + aRowOff;
        const uint32_t bB = stA + OPBYTES + bRowOff;

        #pragma unroll
        for (int ks = 0; ks < 4; ks++) {
            const uint32_t aoff = ((uint32_t)(ks*2) + ahalf ^ lx) << 4;
            const uint32_t boff = ((uint32_t)(ks*2) + bhalf ^ lx) << 4;
            uint32_t af[4][4], bf[4][2];
            #pragma unroll
            for (int mt = 0; mt < 4; mt++)
                ldmatrix_x4(af[mt], aB + (uint32_t)(mt*2048) + aoff);
            #pragma unroll
            for (int nt = 0; nt < 4; nt++)
                ldmatrix_x2(bf[nt], bB + (uint32_t)(nt*1024) + boff);
            #pragma unroll
            for (int mt = 0; mt < 4; mt++)
                #pragma unroll
                for (int nt = 0; nt < 4; nt++)
                    mma_bf16(acc[mt][nt], af[mt], bf[nt]);
        }

        issue_chunk(c + 3);
    }

    // epilogue: m16n8 accum -> rows lane>>2 (+8), cols 2*(lane&3)(+1)
    const int mrow0 = bM + wr*64 + (lane >> 2);
    #pragma unroll
    for (int nt = 0; nt < 4; nt++) {
        const int gcol = bN + wc*32 + nt*8 + (lane & 3)*2;
        const float2 bz = *(const float2*)(bias + gcol);
        float* dstbase;
        int h = 0, d0 = 0;
        if (MODE == 0) {
            const int which = gcol >> 10;
            const int rem = gcol & 1023;
            h = rem >> 6; d0 = rem & 63;
            dstbase = (which == 0) ? g_q : (which == 1 ? g_k : g_v);
        } else {
            dstbase = out;
        }
        #pragma unroll
        for (int mt = 0; mt < 4; mt++) {
            #pragma unroll
            for (int h2 = 0; h2 < 2; h2++) {
                const int row = mrow0 + mt*16 + h2*8;
                float2 v;
                v.x = acc[mt][nt][h2*2 + 0] + bz.x;
                v.y = acc[mt][nt][h2*2 + 1] + bz.y;
                if (MODE == 0) {
                    const int b_ = row >> 11, t_ = row & (TT - 1);
                    *(float2*)(dstbase + ((size_t)(b_*HH + h)*TT + t_)*DD + d0) = v;
                } else {
                    *(float2*)(dstbase + (size_t)row * CC + gcol) = v;
                }
            }
        }
    }
}

// ---------------------------------------------------------------------------
// Flash attention (fp32 SIMT, float4-vectorized LDS) — writes bf16 hi/lo
// KV pitch 68 floats: 16B-aligned rows, odd-in-16B-units -> conflict-free.
// ---------------------------------------------------------------------------
#define KVP 68
#define ATT_SMEM ((64*64 + 64*KVP + 64*64) * 4)

__global__ __launch_bounds__(128, 4)
void attn_kernel()
{
    extern __shared__ float sm[];
    float* Qs  = sm;                     // [64][64]
    float* KVs = sm + 64*64;             // [64][KVP]
    float* Ps  = sm + 64*64 + 64*KVP;    // [64][64]

    const int tid = threadIdx.x;
    const int tx = tid & 15, ty = tid >> 4;
    const int qb = blockIdx.x;
    const int bh = blockIdx.y;
    const int b_ = bh >> 4, h = bh & 15;

    const float* Qg = g_q + ((size_t)bh * TT + qb*64) * DD;
    const float* Kg = g_k + (size_t)bh * TT * DD;
    const float* Vg = g_v + (size_t)bh * TT * DD;

    #pragma unroll
    for (int p = 0; p < 8; p++) {
        int idx = (p*128 + tid) * 4;
        *(float4*)(Qs + idx) = *(const float4*)(Qg + idx);
    }

    float m_i[8], l_i[8], o[8][4];
    #pragma unroll
    for (int i = 0; i < 8; i++) {
        m_i[i] = __int_as_float(0xff800000);
        l_i[i] = 0.f;
        #pragma unroll
        for (int j = 0; j < 4; j++) o[i][j] = 0.f;
    }

    const float scale = 0.125f;

    for (int kt = 0; kt < TT/64; kt++) {
        __syncthreads();
        {
            const float* src = Kg + (size_t)kt * 64 * DD;
            #pragma unroll
            for (int p = 0; p < 8; p++) {
                int idx = (p*128 + tid) * 4;
                int c = idx >> 6, k0 = idx & 63;
                *(float4*)(KVs + c*KVP + k0) = *(const float4*)(src + idx);
            }
        }
        __syncthreads();

        float s[8][4];
        #pragma unroll
        for (int i = 0; i < 8; i++)
            #pragma unroll
            for (int j = 0; j < 4; j++) s[i][j] = 0.f;

        #pragma unroll 4
        for (int k = 0; k < 64; k += 4) {
            float4 kk4[4];
            #pragma unroll
            for (int j = 0; j < 4; j++)
                kk4[j] = *(const float4*)(KVs + (tx + 16*j)*KVP + k);
            #pragma unroll
            for (int i = 0; i < 8; i++) {
                float4 q4 = *(const float4*)(Qs + (ty*8 + i)*64 + k);
                #pragma unroll
                for (int j = 0; j < 4; j++) {
                    s[i][j] += q4.x*kk4[j].x;
                    s[i][j] += q4.y*kk4[j].y;
                    s[i][j] += q4.z*kk4[j].z;
                    s[i][j] += q4.w*kk4[j].w;
                }
            }
        }

        #pragma unroll
        for (int i = 0; i < 8; i++) {
            #pragma unroll
            for (int j = 0; j < 4; j++) s[i][j] *= scale;
            float mx = fmaxf(fmaxf(s[i][0], s[i][1]), fmaxf(s[i][2], s[i][3]));
            mx = fmaxf(mx, __shfl_xor_sync(0xffffffffu, mx, 8));
            mx = fmaxf(mx, __shfl_xor_sync(0xffffffffu, mx, 4));
            mx = fmaxf(mx, __shfl_xor_sync(0xffffffffu, mx, 2));
            mx = fmaxf(mx, __shfl_xor_sync(0xffffffffu, mx, 1));
            float mnew  = fmaxf(m_i[i], mx);
            float alpha = __expf(m_i[i] - mnew);
            m_i[i] = mnew;
            float lsum = 0.f;
            #pragma unroll
            for (int j = 0; j < 4; j++) {
                float p = __expf(s[i][j] - mnew);
                Ps[(ty*8 + i)*64 + tx + 16*j] = p;
                lsum += p;
            }
            lsum += __shfl_xor_sync(0xffffffffu, lsum, 8);
            lsum += __shfl_xor_sync(0xffffffffu, lsum, 4);
            lsum += __shfl_xor_sync(0xffffffffu, lsum, 2);
            lsum += __shfl_xor_sync(0xffffffffu, lsum, 1);
            l_i[i] = l_i[i] * alpha + lsum;
            #pragma unroll
            for (int j = 0; j < 4; j++) o[i][j] *= alpha;
        }
        __syncthreads();

        {
            const float* src = Vg + (size_t)kt * 64 * DD;
            #pragma unroll
            for (int p = 0; p < 8; p++) {
                int idx = (p*128 + tid) * 4;
                int c = idx >> 6, k0 = idx & 63;
                *(float4*)(KVs + c*KVP + k0) = *(const float4*)(src + idx);
            }
        }
        __syncthreads();

        #pragma unroll 2
        for (int c = 0; c < 64; c += 4) {
            float vv[4][4];
            #pragma unroll
            for (int cc = 0; cc < 4; cc++)
                #pragma unroll
                for (int j = 0; j < 4; j++)
                    vv[cc][j] = KVs[(c + cc)*KVP + tx + 16*j];
            #pragma unroll
            for (int i = 0; i < 8; i++) {
                float4 p4 = *(const float4*)(Ps + (ty*8 + i)*64 + c);
                #pragma unroll
                for (int j = 0; j < 4; j++) {
                    o[i][j] += p4.x*vv[0][j];
                    o[i][j] += p4.y*vv[1][j];
                    o[i][j] += p4.z*vv[2][j];
                    o[i][j] += p4.w*vv[3][j];
                }
            }
        }
    }

    // Epilogue: normalize, split to bf16 hi/lo for the proj GEMM
    #pragma unroll
    for (int i = 0; i < 8; i++) {
        float inv = 1.f / l_i[i];
        int t_ = qb*64 + ty*8 + i;
        size_t base = ((size_t)b_ * TT + t_) * CC + h*64;
        #pragma unroll
        for (int j = 0; j < 4; j++) {
            float val = o[i][j] * inv;
            __nv_bfloat16 hbf = __float2bfloat16(val);
            size_t idx = base + tx + 16*j;
            g_ah[idx] = hbf;
            g_al[idx] = __float2bfloat16(val - __bfloat162float(hbf));
        }
    }
}

// ---------------------------------------------------------------------------
extern "C" void kernel_launch(void* const* d_in, const int* in_sizes, int n_in,
                              void* d_out, int out_size)
{
    const float* x      = (const float*)d_in[0];
    const float* qkv_w  = (const float*)d_in[1];
    const float* qkv_b  = (const float*)d_in[2];
    const float* proj_w = (const float*)d_in[3];
    const float* proj_b = (const float*)d_in[4];
    float* out = (float*)d_out;
    (void)in_sizes; (void)n_in; (void)out_size;

    cudaFuncSetAttribute(attn_kernel,
                         cudaFuncAttributeMaxDynamicSharedMemorySize, ATT_SMEM);
    cudaFuncSetAttribute(mma_gemm<0>,
                         cudaFuncAttributeMaxDynamicSharedMemorySize, GSMEM);
    cudaFuncSetAttribute(mma_gemm<1>,
                         cudaFuncAttributeMaxDynamicSharedMemorySize, GSMEM);

    __nv_bfloat16 *xh, *xl, *wh, *wl, *ph_, *pl_, *ah, *al;
    cudaGetSymbolAddress((void**)&xh, g_xh);
    cudaGetSymbolAddress((void**)&xl, g_xl);
    cudaGetSymbolAddress((void**)&wh, g_wh);
    cudaGetSymbolAddress((void**)&wl, g_wl);
    cudaGetSymbolAddress((void**)&ph_, g_ph);
    cudaGetSymbolAddress((void**)&pl_, g_pl);
    cudaGetSymbolAddress((void**)&ah, g_ah);
    cudaGetSymbolAddress((void**)&al, g_al);

    // 1) operand prep
    split_f32_kernel<<<(BT_*CC/4 + 255)/256, 256>>>(x, xh, xl, BT_*CC/4);
    transpose_split_kernel<<<dim3(N3C/32, CC/32), dim3(32, 8)>>>(qkv_w, wh, wl, CC, N3C);
    transpose_split_kernel<<<dim3(CC/32, CC/32), dim3(32, 8)>>>(proj_w, ph_, pl_, CC, CC);

    // 2) QKV GEMM (cp.async-pipelined warp-MMA) -> g_q/g_k/g_v
    mma_gemm<0><<<dim3(N3C/128, BT_/128), 256, GSMEM>>>(xh, xl, wh, wl, qkv_b, nullptr);

    // 3) attention (fp32, vectorized) -> bf16 hi/lo
    attn_kernel<<<dim3(TT/64, BB*HH), 128, ATT_SMEM>>>();

    // 4) output projection -> d_out
    mma_gemm<1><<<dim3(CC/128, BT_/128), 256, GSMEM>>>(ah, al, ph_, pl_, proj_b, out);
}

// round 11
// speedup vs baseline: 3.1409x; 1.6579x over previous
#include <cuda_runtime.h>
#include <cuda_bf16.h>
#include <cstdint>

#define BB 4
#define TT 2048
#define CC 1024
#define HH 16
#define DD 64
#define BT_ (BB*TT)      // 8192
#define N3C (3*CC)       // 3072
#define KK  1024

// ---------------------------------------------------------------------------
// Device scratch
// ---------------------------------------------------------------------------
__device__ __nv_bfloat16 g_qh[BB*HH*TT*DD], g_ql[BB*HH*TT*DD];
__device__ __nv_bfloat16 g_kh[BB*HH*TT*DD], g_kl[BB*HH*TT*DD];
__device__ __nv_bfloat16 g_vh[BB*HH*TT*DD], g_vl[BB*HH*TT*DD];

__device__ __nv_bfloat16 g_xh[BT_*CC], g_xl[BT_*CC];
__device__ __nv_bfloat16 g_wh[N3C*CC], g_wl[N3C*CC];
__device__ __nv_bfloat16 g_ph[CC*CC],  g_pl[CC*CC];
__device__ __nv_bfloat16 g_ah[BT_*CC], g_al[BT_*CC];

// ---------------------------------------------------------------------------
// PTX helpers (plain sm_103-safe: ldmatrix/mma.sync/cp.async)
// ---------------------------------------------------------------------------
__device__ __forceinline__ uint32_t smem_u32(const void* p) {
    uint32_t a;
    asm("{ .reg .u64 t; cvta.to.shared.u64 t, %1; cvt.u32.u64 %0, t; }"
        : "=r"(a) : "l"(p));
    return a;
}
__device__ __forceinline__ void ldmatrix_x4(uint32_t* r, uint32_t addr) {
    asm volatile("ldmatrix.sync.aligned.m8n8.x4.shared.b16 {%0,%1,%2,%3}, [%4];"
                 : "=r"(r[0]), "=r"(r[1]), "=r"(r[2]), "=r"(r[3]) : "r"(addr));
}
__device__ __forceinline__ void ldmatrix_x4t(uint32_t* r, uint32_t addr) {
    asm volatile("ldmatrix.sync.aligned.m8n8.x4.trans.shared.b16 {%0,%1,%2,%3}, [%4];"
                 : "=r"(r[0]), "=r"(r[1]), "=r"(r[2]), "=r"(r[3]) : "r"(addr));
}
__device__ __forceinline__ void ldmatrix_x2(uint32_t* r, uint32_t addr) {
    asm volatile("ldmatrix.sync.aligned.m8n8.x2.shared.b16 {%0,%1}, [%2];"
                 : "=r"(r[0]), "=r"(r[1]) : "r"(addr));
}
__device__ __forceinline__ void mma_bf16(float* d, const uint32_t* a,
                                         uint32_t b0, uint32_t b1) {
    asm volatile(
        "mma.sync.aligned.m16n8k16.row.col.f32.bf16.bf16.f32 "
        "{%0,%1,%2,%3}, {%4,%5,%6,%7}, {%8,%9}, {%0,%1,%2,%3};"
        : "+f"(d[0]), "+f"(d[1]), "+f"(d[2]), "+f"(d[3])
        : "r"(a[0]), "r"(a[1]), "r"(a[2]), "r"(a[3]), "r"(b0), "r"(b1));
}
__device__ __forceinline__ void cp_async16(uint32_t s, const void* g) {
    asm volatile("cp.async.cg.shared.global [%0], [%1], 16;"
                 :: "r"(s), "l"(g) : "memory");
}
#define CP_COMMIT() asm volatile("cp.async.commit_group;" ::: "memory")
#define CP_WAIT1()  asm volatile("cp.async.wait_group 1;" ::: "memory")

__device__ __forceinline__ uint32_t packbf2(float lo, float hi) {
    __nv_bfloat162 t(__float2bfloat16(lo), __float2bfloat16(hi));
    return *(uint32_t*)&t;
}

// ---------------------------------------------------------------------------
// Split helpers
// ---------------------------------------------------------------------------
__global__ void split_f32_kernel(const float* __restrict__ in,
                                 __nv_bfloat16* __restrict__ hi,
                                 __nv_bfloat16* __restrict__ lo, int n4)
{
    int i = blockIdx.x * blockDim.x + threadIdx.x;
    if (i >= n4) return;
    float4 v = ((const float4*)in)[i];
    __nv_bfloat16 h0 = __float2bfloat16(v.x);
    __nv_bfloat16 h1 = __float2bfloat16(v.y);
    __nv_bfloat16 h2 = __float2bfloat16(v.z);
    __nv_bfloat16 h3 = __float2bfloat16(v.w);
    __nv_bfloat162* hp = (__nv_bfloat162*)(hi + i*4);
    __nv_bfloat162* lp = (__nv_bfloat162*)(lo + i*4);
    hp[0] = __nv_bfloat162(h0, h1);
    hp[1] = __nv_bfloat162(h2, h3);
    lp[0] = __nv_bfloat162(__float2bfloat16(v.x - __bfloat162float(h0)),
                           __float2bfloat16(v.y - __bfloat162float(h1)));
    lp[1] = __nv_bfloat162(__float2bfloat16(v.z - __bfloat162float(h2)),
                           __float2bfloat16(v.w - __bfloat162float(h3)));
}

__global__ void transpose_split_kernel(const float* __restrict__ in,
                                       __nv_bfloat16* __restrict__ hi,
                                       __nv_bfloat16* __restrict__ lo,
                                       int R, int C)
{
    __shared__ float s[32][33];
    int c0 = blockIdx.x * 32, r0 = blockIdx.y * 32;
    int tx = threadIdx.x, ty = threadIdx.y;
    #pragma unroll
    for (int i = ty; i < 32; i += 8)
        s[i][tx] = in[(size_t)(r0 + i) * C + c0 + tx];
    __syncthreads();
    #pragma unroll
    for (int i = ty; i < 32; i += 8) {
        float v = s[tx][i];
        __nv_bfloat16 h = __float2bfloat16(v);
        size_t o = (size_t)(c0 + i) * R + r0 + tx;
        hi[o] = h;
        lo[o] = __float2bfloat16(v - __bfloat162float(h));
    }
}

// ---------------------------------------------------------------------------
// Warp-MMA bf16 GEMM (error-compensated 3-pass). 128x128 tile, 8 warps,
// K-chunk 64, 3-stage cp.async, 2 CTAs/SM.
// MODE 0: bias + split-bf16 scatter to g_{q,k,v}{h,l}.  MODE 1: bias + f32 out.
// ---------------------------------------------------------------------------
#define KC       64
#define OPBYTES  16384
#define STG_B    (2*OPBYTES)
#define GSTAGES  3
#define GSMEM    (GSTAGES*STG_B)       // 96 KB
#define CHUNKS   48

template<int MODE>
__global__ __launch_bounds__(256, 2)
void mma_gemm(const __nv_bfloat16* __restrict__ Ah, const __nv_bfloat16* __restrict__ Al,
              const __nv_bfloat16* __restrict__ Bh, const __nv_bfloat16* __restrict__ Bl,
              const float* __restrict__ bias, float* __restrict__ out)
{
    extern __shared__ __align__(128) char gsm[];
    const uint32_t sbase = smem_u32(gsm);

    const int tid  = threadIdx.x;
    const int lane = tid & 31, wid = tid >> 5;
    const int wr = wid >> 2, wc = wid & 3;
    const int bM = blockIdx.y * 128, bN = blockIdx.x * 128;

    const int ldRow = tid >> 1;
    const int ldS0  = (tid & 1) * 4;
    const uint32_t ldRowOff = (uint32_t)ldRow * 128;
    const uint32_t ldXor    = (uint32_t)(ldRow & 7);

    float acc[4][4][4];
    #pragma unroll
    for (int mt = 0; mt < 4; mt++)
        #pragma unroll
        for (int nt = 0; nt < 4; nt++)
            #pragma unroll
            for (int r = 0; r < 4; r++) acc[mt][nt][r] = 0.f;

    auto issue_chunk = [&](int g) {
        if (g < CHUNKS) {
            const int pass = g >> 4;
            const int k0 = (g & 15) * KC;
            const __nv_bfloat16* Ap = (pass == 1) ? Al : Ah;
            const __nv_bfloat16* Bp = (pass == 2) ? Bl : Bh;
            const uint32_t st = sbase + (uint32_t)(g % GSTAGES) * STG_B;
            const char* ga = (const char*)(Ap + (size_t)(bM + ldRow) * KK + k0) + ldS0*16;
            const char* gb = (const char*)(Bp + (size_t)(bN + ldRow) * KK + k0) + ldS0*16;
            #pragma unroll
            for (int i = 0; i < 4; i++) {
                const uint32_t sw = (uint32_t)(((ldS0 + i) ^ ldXor) << 4);
                cp_async16(st + ldRowOff + sw,           ga + i*16);
                cp_async16(st + OPBYTES + ldRowOff + sw, gb + i*16);
            }
        }
        CP_COMMIT();
    };

    issue_chunk(0);
    issue_chunk(1);

    const uint32_t aRowOff = (uint32_t)(wr*64 + (lane & 15)) * 128;
    const uint32_t bRowOff = (uint32_t)(wc*32 + (lane & 7)) * 128;
    const uint32_t ahalf = (uint32_t)(lane >> 4);
    const uint32_t bhalf = (uint32_t)((lane >> 3) & 1);
    const uint32_t lx    = (uint32_t)(lane & 7);

    for (int c = 0; c < CHUNKS; c++) {
        CP_WAIT1();
        __syncthreads();
        issue_chunk(c + 2);

        const uint32_t stA = sbase + (uint32_t)(c % GSTAGES) * STG_B;
        const uint32_t aB = stA + aRowOff;
        const uint32_t bB = stA + OPBYTES + bRowOff;

        #pragma unroll
        for (int ks = 0; ks < 4; ks++) {
            const uint32_t aoff = ((uint32_t)(ks*2) + ahalf ^ lx) << 4;
            const uint32_t boff = ((uint32_t)(ks*2) + bhalf ^ lx) << 4;
            uint32_t af[4][4], bf[4][2];
            #pragma unroll
            for (int mt = 0; mt < 4; mt++)
                ldmatrix_x4(af[mt], aB + (uint32_t)(mt*2048) + aoff);
            #pragma unroll
            for (int nt = 0; nt < 4; nt++)
                ldmatrix_x2(bf[nt], bB + (uint32_t)(nt*1024) + boff);
            #pragma unroll
            for (int mt = 0; mt < 4; mt++)
                #pragma unroll
                for (int nt = 0; nt < 4; nt++)
                    mma_bf16(acc[mt][nt], af[mt], bf[nt][0], bf[nt][1]);
        }
    }

    const int mrow0 = bM + wr*64 + (lane >> 2);
    #pragma unroll
    for (int nt = 0; nt < 4; nt++) {
        const int gcol = bN + wc*32 + nt*8 + (lane & 3)*2;
        const float2 bz = *(const float2*)(bias + gcol);
        __nv_bfloat16 *dh = nullptr, *dl = nullptr;
        int h = 0, d0 = 0;
        if (MODE == 0) {
            const int which = gcol >> 10;
            const int rem = gcol & 1023;
            h = rem >> 6; d0 = rem & 63;
            dh = (which == 0) ? g_qh : (which == 1 ? g_kh : g_vh);
            dl = (which == 0) ? g_ql : (which == 1 ? g_kl : g_vl);
        }
        #pragma unroll
        for (int mt = 0; mt < 4; mt++) {
            #pragma unroll
            for (int h2 = 0; h2 < 2; h2++) {
                const int row = mrow0 + mt*16 + h2*8;
                float vx = acc[mt][nt][h2*2 + 0] + bz.x;
                float vy = acc[mt][nt][h2*2 + 1] + bz.y;
                if (MODE == 0) {
                    const int b_ = row >> 11, t_ = row & (TT - 1);
                    const size_t idx = ((size_t)(b_*HH + h)*TT + t_)*DD + d0;
                    __nv_bfloat16 hx = __float2bfloat16(vx);
                    __nv_bfloat16 hy = __float2bfloat16(vy);
                    *(__nv_bfloat162*)(dh + idx) = __nv_bfloat162(hx, hy);
                    *(__nv_bfloat162*)(dl + idx) = __nv_bfloat162(
                        __float2bfloat16(vx - __bfloat162float(hx)),
                        __float2bfloat16(vy - __bfloat162float(hy)));
                } else {
                    float2 v; v.x = vx; v.y = vy;
                    *(float2*)(out + (size_t)row * CC + gcol) = v;
                }
            }
        }
    }
}

// ---------------------------------------------------------------------------
// Tensor-core flash attention. CTA = 128 thr (4 warps), q-tile 64, kv-tile 64.
// 3-stage KV buffers, 2-deep cp.async pipeline (issue kt+2 at kt -> stage
// (kt+2)%3 != read stage kt%3; last readers of that stage are behind the
// top-of-loop barrier). This fixes the round-7 race (kt+3 -> stage kt%3).
// ---------------------------------------------------------------------------
#define AQ_B    16384                  // Qh+Ql (8KB each)
#define KV_STG  32768                  // Kh,Kl,Vh,Vl (8KB each)
#define AT_SMEM (AQ_B + 3*KV_STG)      // 112 KB
#define NKT     (TT/64)                // 32

__global__ __launch_bounds__(128, 2)
void attn_mma_kernel()
{
    extern __shared__ __align__(128) char asm_[];
    const uint32_t sb = smem_u32(asm_);
    const uint32_t sQh = sb, sQl = sb + 8192, sKV = sb + AQ_B;

    const int tid = threadIdx.x;
    const int lane = tid & 31, w = tid >> 5;
    const int qb = blockIdx.x;          // 0..31
    const int bh = blockIdx.y;          // 0..63
    const int b_ = bh >> 4, h = bh & 15;

    const __nv_bfloat16* Qhg = g_qh + ((size_t)bh*TT + qb*64)*DD;
    const __nv_bfloat16* Qlg = g_ql + ((size_t)bh*TT + qb*64)*DD;
    const size_t kvb = (size_t)bh*TT*DD;

    const int ldRow = tid >> 1;
    const int ldS0  = (tid & 1) * 4;
    const uint32_t ldRowOff = (uint32_t)ldRow * 128;
    const uint32_t ldXor    = (uint32_t)(ldRow & 7);
    auto load_tile = [&](uint32_t dst, const __nv_bfloat16* src) {
        const char* g = (const char*)(src + (size_t)ldRow * DD) + ldS0*16;
        #pragma unroll
        for (int i = 0; i < 4; i++) {
            const uint32_t sw = (uint32_t)(((ldS0 + i) ^ ldXor) << 4);
            cp_async16(dst + ldRowOff + sw, g + i*16);
        }
    };
    auto issue_kv = [&](int kt) {
        if (kt < NKT) {
            const uint32_t st = sKV + (uint32_t)(kt % 3) * KV_STG;
            const size_t off = kvb + (size_t)kt*64*DD;
            load_tile(st,         g_kh + off);
            load_tile(st + 8192,  g_kl + off);
            load_tile(st + 16384, g_vh + off);
            load_tile(st + 24576, g_vl + off);
        }
        CP_COMMIT();
    };

    // prologue: group0 = Q + KV0; group1 = KV1   (2-deep pipeline)
    load_tile(sQh, Qhg);
    load_tile(sQl, Qlg);
    issue_kv(0);
    issue_kv(1);

    const uint32_t lx = (uint32_t)(lane & 7);

    uint32_t qhf[4][4], qlf[4][4];
    float o[8][4];
    #pragma unroll
    for (int nt = 0; nt < 8; nt++)
        #pragma unroll
        for (int r = 0; r < 4; r++) o[nt][r] = 0.f;
    float m0 = -1e30f, m1 = -1e30f, l0 = 0.f, l1 = 0.f;
    const float scale = 0.125f;

    for (int kt = 0; kt < NKT; kt++) {
        CP_WAIT1();
        __syncthreads();
        if (kt == 0) {
            const uint32_t qRowOff = (uint32_t)(w*16 + (lane & 15)) * 128;
            #pragma unroll
            for (int ks = 0; ks < 4; ks++) {
                const uint32_t off = (((uint32_t)(ks*2) + (lane >> 4)) ^ lx) << 4;
                ldmatrix_x4(qhf[ks], sQh + qRowOff + off);
                ldmatrix_x4(qlf[ks], sQl + qRowOff + off);
            }
        }
        issue_kv(kt + 2);

        const uint32_t st = sKV + (uint32_t)(kt % 3) * KV_STG;

        // ---- S = QhKh + QlKh + QhKl ----
        float s[8][4];
        #pragma unroll
        for (int nt = 0; nt < 8; nt++)
            #pragma unroll
            for (int r = 0; r < 4; r++) s[nt][r] = 0.f;

        const uint32_t kRowOff = (uint32_t)(lane & 15) * 128;
        #pragma unroll
        for (int ks = 0; ks < 4; ks++) {
            const uint32_t koff = (((uint32_t)(ks*2) + (lane >> 4)) ^ lx) << 4;
            uint32_t kf[4][4];
            #pragma unroll
            for (int p = 0; p < 4; p++)
                ldmatrix_x4(kf[p], st + (uint32_t)(p*2048) + kRowOff + koff);
            #pragma unroll
            for (int nt = 0; nt < 8; nt++) {
                const int p = nt >> 1, q = (nt & 1);
                mma_bf16(s[nt], qhf[ks], kf[p][q], kf[p][q + 2]);
            }
            #pragma unroll
            for (int nt = 0; nt < 8; nt++) {
                const int p = nt >> 1, q = (nt & 1);
                mma_bf16(s[nt], qlf[ks], kf[p][q], kf[p][q + 2]);
            }
            #pragma unroll
            for (int p = 0; p < 4; p++)
                ldmatrix_x4(kf[p], st + 8192 + (uint32_t)(p*2048) + kRowOff + koff);
            #pragma unroll
            for (int nt = 0; nt < 8; nt++) {
                const int p = nt >> 1, q = (nt & 1);
                mma_bf16(s[nt], qhf[ks], kf[p][q], kf[p][q + 2]);
            }
        }

        // ---- online softmax in fragments (rows lane>>2 and +8) ----
        float rm0 = -1e30f, rm1 = -1e30f;
        #pragma unroll
        for (int nt = 0; nt < 8; nt++) {
            #pragma unroll
            for (int r = 0; r < 4; r++) s[nt][r] *= scale;
            rm0 = fmaxf(rm0, fmaxf(s[nt][0], s[nt][1]));
            rm1 = fmaxf(rm1, fmaxf(s[nt][2], s[nt][3]));
        }
        rm0 = fmaxf(rm0, __shfl_xor_sync(0xffffffffu, rm0, 1));
        rm0 = fmaxf(rm0, __shfl_xor_sync(0xffffffffu, rm0, 2));
        rm1 = fmaxf(rm1, __shfl_xor_sync(0xffffffffu, rm1, 1));
        rm1 = fmaxf(rm1, __shfl_xor_sync(0xffffffffu, rm1, 2));
        const float mn0 = fmaxf(m0, rm0), mn1 = fmaxf(m1, rm1);
        const float al0 = __expf(m0 - mn0), al1 = __expf(m1 - mn1);
        m0 = mn0; m1 = mn1;

        uint32_t php[4][4], plp[4][4];
        float ls0 = 0.f, ls1 = 0.f;
        #pragma unroll
        for (int nt = 0; nt < 8; nt++) {
            float p0 = __expf(s[nt][0] - m0);
            float p1 = __expf(s[nt][1] - m0);
            float p2 = __expf(s[nt][2] - m1);
            float p3 = __expf(s[nt][3] - m1);
            ls0 += p0 + p1; ls1 += p2 + p3;
            __nv_bfloat16 h0 = __float2bfloat16(p0), h1 = __float2bfloat16(p1);
            __nv_bfloat16 h2 = __float2bfloat16(p2), h3 = __float2bfloat16(p3);
            const int kk = nt >> 1;
            __nv_bfloat162 hp01(h0, h1), hp23(h2, h3);
            php[kk][(nt&1)*2 + 0] = *(uint32_t*)&hp01;
            php[kk][(nt&1)*2 + 1] = *(uint32_t*)&hp23;
            plp[kk][(nt&1)*2 + 0] = packbf2(p0 - __bfloat162float(h0),
                                            p1 - __bfloat162float(h1));
            plp[kk][(nt&1)*2 + 1] = packbf2(p2 - __bfloat162float(h2),
                                            p3 - __bfloat162float(h3));
        }
        ls0 += __shfl_xor_sync(0xffffffffu, ls0, 1);
        ls0 += __shfl_xor_sync(0xffffffffu, ls0, 2);
        ls1 += __shfl_xor_sync(0xffffffffu, ls1, 1);
        ls1 += __shfl_xor_sync(0xffffffffu, ls1, 2);
        l0 = l0 * al0 + ls0;
        l1 = l1 * al1 + ls1;
        #pragma unroll
        for (int nt = 0; nt < 8; nt++) {
            o[nt][0] *= al0; o[nt][1] *= al0;
            o[nt][2] *= al1; o[nt][3] *= al1;
        }

        // ---- O += PhVh + PlVh + PhVl ----
        const uint32_t vRow = (uint32_t)(((lane >> 3) & 1) * 8 + (lane & 7));
        #pragma unroll
        for (int kk = 0; kk < 4; kk++) {
            uint32_t vf[4][4];
            const uint32_t vrOff = ((uint32_t)(kk*16) + vRow) * 128;
            #pragma unroll
            for (int p = 0; p < 4; p++) {
                const uint32_t coff = (((uint32_t)(p*2) + (lane >> 4)) ^ lx) << 4;
                ldmatrix_x4t(vf[p], st + 16384 + vrOff + coff);
            }
            #pragma unroll
            for (int nt = 0; nt < 8; nt++) {
                const int p = nt >> 1, q = (nt & 1) * 2;
                mma_bf16(o[nt], php[kk], vf[p][q], vf[p][q + 1]);
            }
            #pragma unroll
            for (int nt = 0; nt < 8; nt++) {
                const int p = nt >> 1, q = (nt & 1) * 2;
                mma_bf16(o[nt], plp[kk], vf[p][q], vf[p][q + 1]);
            }
            #pragma unroll
            for (int p = 0; p < 4; p++) {
                const uint32_t coff = (((uint32_t)(p*2) + (lane >> 4)) ^ lx) << 4;
                ldmatrix_x4t(vf[p], st + 24576 + vrOff + coff);
            }
            #pragma unroll
            for (int nt = 0; nt < 8; nt++) {
                const int p = nt >> 1, q = (nt & 1) * 2;
                mma_bf16(o[nt], php[kk], vf[p][q], vf[p][q + 1]);
            }
        }
    }

    // ---- epilogue: normalize, split bf16 hi/lo into g_ah/g_al ----
    const float inv0 = 1.f / l0, inv1 = 1.f / l1;
    const int r0 = w*16 + (lane >> 2);
    const int t0 = qb*64 + r0;
    const size_t base0 = ((size_t)b_*TT + t0)*CC + h*64;
    const size_t base1 = base0 + 8*(size_t)CC;
    #pragma unroll
    for (int nt = 0; nt < 8; nt++) {
        const int col = nt*8 + (lane & 3)*2;
        float v0 = o[nt][0]*inv0, v1 = o[nt][1]*inv0;
        float v2 = o[nt][2]*inv1, v3 = o[nt][3]*inv1;
        __nv_bfloat16 h0 = __float2bfloat16(v0), h1 = __float2bfloat16(v1);
        __nv_bfloat16 h2 = __float2bfloat16(v2), h3 = __float2bfloat16(v3);
        *(__nv_bfloat162*)(g_ah + base0 + col) = __nv_bfloat162(h0, h1);
        *(__nv_bfloat162*)(g_al + base0 + col) = __nv_bfloat162(
            __float2bfloat16(v0 - __bfloat162float(h0)),
            __float2bfloat16(v1 - __bfloat162float(h1)));
        *(__nv_bfloat162*)(g_ah + base1 + col) = __nv_bfloat162(h2, h3);
        *(__nv_bfloat162*)(g_al + base1 + col) = __nv_bfloat162(
            __float2bfloat16(v2 - __bfloat162float(h2)),
            __float2bfloat16(v3 - __bfloat162float(h3)));
    }
}

// ---------------------------------------------------------------------------
extern "C" void kernel_launch(void* const* d_in, const int* in_sizes, int n_in,
                              void* d_out, int out_size)
{
    const float* x      = (const float*)d_in[0];
    const float* qkv_w  = (const float*)d_in[1];
    const float* qkv_b  = (const float*)d_in[2];
    const float* proj_w = (const float*)d_in[3];
    const float* proj_b = (const float*)d_in[4];
    float* out = (float*)d_out;
    (void)in_sizes; (void)n_in; (void)out_size;

    cudaFuncSetAttribute(mma_gemm<0>,
                         cudaFuncAttributeMaxDynamicSharedMemorySize, GSMEM);
    cudaFuncSetAttribute(mma_gemm<1>,
                         cudaFuncAttributeMaxDynamicSharedMemorySize, GSMEM);
    cudaFuncSetAttribute(attn_mma_kernel,
                         cudaFuncAttributeMaxDynamicSharedMemorySize, AT_SMEM);

    __nv_bfloat16 *xh, *xl, *wh, *wl, *ph_, *pl_, *ah, *al;
    cudaGetSymbolAddress((void**)&xh, g_xh);
    cudaGetSymbolAddress((void**)&xl, g_xl);
    cudaGetSymbolAddress((void**)&wh, g_wh);
    cudaGetSymbolAddress((void**)&wl, g_wl);
    cudaGetSymbolAddress((void**)&ph_, g_ph);
    cudaGetSymbolAddress((void**)&pl_, g_pl);
    cudaGetSymbolAddress((void**)&ah, g_ah);
    cudaGetSymbolAddress((void**)&al, g_al);

    // 1) operand prep
    split_f32_kernel<<<(BT_*CC/4 + 255)/256, 256>>>(x, xh, xl, BT_*CC/4);
    transpose_split_kernel<<<dim3(N3C/32, CC/32), dim3(32, 8)>>>(qkv_w, wh, wl, CC, N3C);
    transpose_split_kernel<<<dim3(CC/32, CC/32), dim3(32, 8)>>>(proj_w, ph_, pl_, CC, CC);

    // 2) QKV GEMM -> split-bf16 q/k/v [B,H,T,D]
    mma_gemm<0><<<dim3(N3C/128, BT_/128), 256, GSMEM>>>(xh, xl, wh, wl, qkv_b, nullptr);

    // 3) tensor-core flash attention -> split-bf16 attention output
    attn_mma_kernel<<<dim3(TT/64, BB*HH), 128, AT_SMEM>>>();

    // 4) output projection -> d_out
    mma_gemm<1><<<dim3(CC/128, BT_/128), 256, GSMEM>>>(ah, al, ph_, pl_, proj_b, out);
}

// round 12
// speedup vs baseline: 3.6328x; 1.1566x over previous
#include <cuda_runtime.h>
#include <cuda_bf16.h>
#include <cuda_fp16.h>
#include <cstdint>

#define BB 4
#define TT 2048
#define CC 1024
#define HH 16
#define DD 64
#define BT_ (BB*TT)      // 8192
#define N3C (3*CC)       // 3072
#define KK  1024

// ---------------------------------------------------------------------------
// Device scratch
// ---------------------------------------------------------------------------
__device__ __nv_bfloat16 g_qh[BB*HH*TT*DD], g_ql[BB*HH*TT*DD];
__device__ __nv_bfloat16 g_kh[BB*HH*TT*DD], g_kl[BB*HH*TT*DD];
__device__ __half        g_vf[BB*HH*TT*DD];              // V single fp16

__device__ __nv_bfloat16 g_xh[BT_*CC], g_xl[BT_*CC];
__device__ __nv_bfloat16 g_wh[N3C*CC], g_wl[N3C*CC];
__device__ __half        g_p16h[CC*CC], g_p16l[CC*CC];   // proj_w^T fp16 hi/lo
__device__ __half        g_a16[BT_*CC];                  // attn out single fp16

// ---------------------------------------------------------------------------
// PTX helpers (plain sm_103-safe: ldmatrix/mma.sync/cp.async)
// ---------------------------------------------------------------------------
__device__ __forceinline__ uint32_t smem_u32(const void* p) {
    uint32_t a;
    asm("{ .reg .u64 t; cvta.to.shared.u64 t, %1; cvt.u32.u64 %0, t; }"
        : "=r"(a) : "l"(p));
    return a;
}
__device__ __forceinline__ void ldmatrix_x4(uint32_t* r, uint32_t addr) {
    asm volatile("ldmatrix.sync.aligned.m8n8.x4.shared.b16 {%0,%1,%2,%3}, [%4];"
                 : "=r"(r[0]), "=r"(r[1]), "=r"(r[2]), "=r"(r[3]) : "r"(addr));
}
__device__ __forceinline__ void ldmatrix_x4t(uint32_t* r, uint32_t addr) {
    asm volatile("ldmatrix.sync.aligned.m8n8.x4.trans.shared.b16 {%0,%1,%2,%3}, [%4];"
                 : "=r"(r[0]), "=r"(r[1]), "=r"(r[2]), "=r"(r[3]) : "r"(addr));
}
__device__ __forceinline__ void ldmatrix_x2(uint32_t* r, uint32_t addr) {
    asm volatile("ldmatrix.sync.aligned.m8n8.x2.shared.b16 {%0,%1}, [%2];"
                 : "=r"(r[0]), "=r"(r[1]) : "r"(addr));
}
__device__ __forceinline__ void mma_bf16(float* d, const uint32_t* a,
                                         uint32_t b0, uint32_t b1) {
    asm volatile(
        "mma.sync.aligned.m16n8k16.row.col.f32.bf16.bf16.f32 "
        "{%0,%1,%2,%3}, {%4,%5,%6,%7}, {%8,%9}, {%0,%1,%2,%3};"
        : "+f"(d[0]), "+f"(d[1]), "+f"(d[2]), "+f"(d[3])
        : "r"(a[0]), "r"(a[1]), "r"(a[2]), "r"(a[3]), "r"(b0), "r"(b1));
}
__device__ __forceinline__ void mma_f16(float* d, const uint32_t* a,
                                        uint32_t b0, uint32_t b1) {
    asm volatile(
        "mma.sync.aligned.m16n8k16.row.col.f32.f16.f16.f32 "
        "{%0,%1,%2,%3}, {%4,%5,%6,%7}, {%8,%9}, {%0,%1,%2,%3};"
        : "+f"(d[0]), "+f"(d[1]), "+f"(d[2]), "+f"(d[3])
        : "r"(a[0]), "r"(a[1]), "r"(a[2]), "r"(a[3]), "r"(b0), "r"(b1));
}
__device__ __forceinline__ void cp_async16(uint32_t s, const void* g) {
    asm volatile("cp.async.cg.shared.global [%0], [%1], 16;"
                 :: "r"(s), "l"(g) : "memory");
}
#define CP_COMMIT() asm volatile("cp.async.commit_group;" ::: "memory")
#define CP_WAIT1()  asm volatile("cp.async.wait_group 1;" ::: "memory")

__device__ __forceinline__ uint32_t packhf2(float lo, float hi) {
    __half2 t(__float2half(lo), __float2half(hi));
    return *(uint32_t*)&t;
}

// ---------------------------------------------------------------------------
// Split helpers
// ---------------------------------------------------------------------------
__global__ void split_f32_kernel(const float* __restrict__ in,
                                 __nv_bfloat16* __restrict__ hi,
                                 __nv_bfloat16* __restrict__ lo, int n4)
{
    int i = blockIdx.x * blockDim.x + threadIdx.x;
    if (i >= n4) return;
    float4 v = ((const float4*)in)[i];
    __nv_bfloat16 h0 = __float2bfloat16(v.x);
    __nv_bfloat16 h1 = __float2bfloat16(v.y);
    __nv_bfloat16 h2 = __float2bfloat16(v.z);
    __nv_bfloat16 h3 = __float2bfloat16(v.w);
    __nv_bfloat162* hp = (__nv_bfloat162*)(hi + i*4);
    __nv_bfloat162* lp = (__nv_bfloat162*)(lo + i*4);
    hp[0] = __nv_bfloat162(h0, h1);
    hp[1] = __nv_bfloat162(h2, h3);
    lp[0] = __nv_bfloat162(__float2bfloat16(v.x - __bfloat162float(h0)),
                           __float2bfloat16(v.y - __bfloat162float(h1)));
    lp[1] = __nv_bfloat162(__float2bfloat16(v.z - __bfloat162float(h2)),
                           __float2bfloat16(v.w - __bfloat162float(h3)));
}

// in [R, C] f32 -> out [C, R] bf16 hi/lo  (qkv_w)
__global__ void transpose_split_kernel(const float* __restrict__ in,
                                       __nv_bfloat16* __restrict__ hi,
                                       __nv_bfloat16* __restrict__ lo,
                                       int R, int C)
{
    __shared__ float s[32][33];
    int c0 = blockIdx.x * 32, r0 = blockIdx.y * 32;
    int tx = threadIdx.x, ty = threadIdx.y;
    #pragma unroll
    for (int i = ty; i < 32; i += 8)
        s[i][tx] = in[(size_t)(r0 + i) * C + c0 + tx];
    __syncthreads();
    #pragma unroll
    for (int i = ty; i < 32; i += 8) {
        float v = s[tx][i];
        __nv_bfloat16 h = __float2bfloat16(v);
        size_t o = (size_t)(c0 + i) * R + r0 + tx;
        hi[o] = h;
        lo[o] = __float2bfloat16(v - __bfloat162float(h));
    }
}

// in [R, C] f32 -> out [C, R] fp16 hi/lo  (proj_w)
__global__ void transpose_split_f16_kernel(const float* __restrict__ in,
                                           __half* __restrict__ hi,
                                           __half* __restrict__ lo,
                                           int R, int C)
{
    __shared__ float s[32][33];
    int c0 = blockIdx.x * 32, r0 = blockIdx.y * 32;
    int tx = threadIdx.x, ty = threadIdx.y;
    #pragma unroll
    for (int i = ty; i < 32; i += 8)
        s[i][tx] = in[(size_t)(r0 + i) * C + c0 + tx];
    __syncthreads();
    #pragma unroll
    for (int i = ty; i < 32; i += 8) {
        float v = s[tx][i];
        __half h = __float2half(v);
        size_t o = (size_t)(c0 + i) * R + r0 + tx;
        hi[o] = h;
        lo[o] = __float2half(v - __half2float(h));
    }
}

// ---------------------------------------------------------------------------
// Warp-MMA GEMM. 128x128 tile, 8 warps, K-chunk 64, 3-stage cp.async, 2 CTA/SM.
// MODE 0: bf16 3-pass (AhBh+AlBh+AhBl); epilogue bias + Q/K bf16-split, V fp16.
// MODE 1: fp16 2-pass (A·Bh + A·Bl, A single fp16); epilogue bias + f32 out.
// ---------------------------------------------------------------------------
#define KC       64
#define OPBYTES  16384
#define STG_B    (2*OPBYTES)
#define GSTAGES  3
#define GSMEM    (GSTAGES*STG_B)       // 96 KB

template<int MODE>
__global__ __launch_bounds__(256, 2)
void mma_gemm(const __nv_bfloat16* __restrict__ Ah, const __nv_bfloat16* __restrict__ Al,
              const __nv_bfloat16* __restrict__ Bh, const __nv_bfloat16* __restrict__ Bl,
              const float* __restrict__ bias, float* __restrict__ out)
{
    constexpr int NCH = (MODE == 0) ? 48 : 32;   // 3 or 2 passes x 16 chunks

    extern __shared__ __align__(128) char gsm[];
    const uint32_t sbase = smem_u32(gsm);

    const int tid  = threadIdx.x;
    const int lane = tid & 31, wid = tid >> 5;
    const int wr = wid >> 2, wc = wid & 3;
    const int bM = blockIdx.y * 128, bN = blockIdx.x * 128;

    const int ldRow = tid >> 1;
    const int ldS0  = (tid & 1) * 4;
    const uint32_t ldRowOff = (uint32_t)ldRow * 128;
    const uint32_t ldXor    = (uint32_t)(ldRow & 7);

    float acc[4][4][4];
    #pragma unroll
    for (int mt = 0; mt < 4; mt++)
        #pragma unroll
        for (int nt = 0; nt < 4; nt++)
            #pragma unroll
            for (int r = 0; r < 4; r++) acc[mt][nt][r] = 0.f;

    auto issue_chunk = [&](int g) {
        if (g < NCH) {
            const int pass = g >> 4;
            const int k0 = (g & 15) * KC;
            const __nv_bfloat16* Ap;
            const __nv_bfloat16* Bp;
            if (MODE == 0) {
                Ap = (pass == 1) ? Al : Ah;
                Bp = (pass == 2) ? Bl : Bh;
            } else {
                Ap = Ah;
                Bp = pass ? Bl : Bh;
            }
            const uint32_t st = sbase + (uint32_t)(g % GSTAGES) * STG_B;
            const char* ga = (const char*)(Ap + (size_t)(bM + ldRow) * KK + k0) + ldS0*16;
            const char* gb = (const char*)(Bp + (size_t)(bN + ldRow) * KK + k0) + ldS0*16;
            #pragma unroll
            for (int i = 0; i < 4; i++) {
                const uint32_t sw = (uint32_t)(((ldS0 + i) ^ ldXor) << 4);
                cp_async16(st + ldRowOff + sw,           ga + i*16);
                cp_async16(st + OPBYTES + ldRowOff + sw, gb + i*16);
            }
        }
        CP_COMMIT();
    };

    issue_chunk(0);
    issue_chunk(1);

    const uint32_t aRowOff = (uint32_t)(wr*64 + (lane & 15)) * 128;
    const uint32_t bRowOff = (uint32_t)(wc*32 + (lane & 7)) * 128;
    const uint32_t ahalf = (uint32_t)(lane >> 4);
    const uint32_t bhalf = (uint32_t)((lane >> 3) & 1);
    const uint32_t lx    = (uint32_t)(lane & 7);

    for (int c = 0; c < NCH; c++) {
        CP_WAIT1();
        __syncthreads();
        issue_chunk(c + 2);

        const uint32_t stA = sbase + (uint32_t)(c % GSTAGES) * STG_B;
        const uint32_t aB = stA + aRowOff;
        const uint32_t bB = stA + OPBYTES + bRowOff;

        #pragma unroll
        for (int ks = 0; ks < 4; ks++) {
            const uint32_t aoff = ((uint32_t)(ks*2) + ahalf ^ lx) << 4;
            const uint32_t boff = ((uint32_t)(ks*2) + bhalf ^ lx) << 4;
            uint32_t af[4][4], bf[4][2];
            #pragma unroll
            for (int mt = 0; mt < 4; mt++)
                ldmatrix_x4(af[mt], aB + (uint32_t)(mt*2048) + aoff);
            #pragma unroll
            for (int nt = 0; nt < 4; nt++)
                ldmatrix_x2(bf[nt], bB + (uint32_t)(nt*1024) + boff);
            #pragma unroll
            for (int mt = 0; mt < 4; mt++)
                #pragma unroll
                for (int nt = 0; nt < 4; nt++) {
                    if (MODE == 0)
                        mma_bf16(acc[mt][nt], af[mt], bf[nt][0], bf[nt][1]);
                    else
                        mma_f16(acc[mt][nt], af[mt], bf[nt][0], bf[nt][1]);
                }
        }
    }

    const int mrow0 = bM + wr*64 + (lane >> 2);
    #pragma unroll
    for (int nt = 0; nt < 4; nt++) {
        const int gcol = bN + wc*32 + nt*8 + (lane & 3)*2;
        const float2 bz = *(const float2*)(bias + gcol);
        __nv_bfloat16 *dh = nullptr, *dl = nullptr;
        int which = 0, h = 0, d0 = 0;
        if (MODE == 0) {
            which = gcol >> 10;
            const int rem = gcol & 1023;
            h = rem >> 6; d0 = rem & 63;
            if (which < 2) {
                dh = (which == 0) ? g_qh : g_kh;
                dl = (which == 0) ? g_ql : g_kl;
            }
        }
        #pragma unroll
        for (int mt = 0; mt < 4; mt++) {
            #pragma unroll
            for (int h2 = 0; h2 < 2; h2++) {
                const int row = mrow0 + mt*16 + h2*8;
                float vx = acc[mt][nt][h2*2 + 0] + bz.x;
                float vy = acc[mt][nt][h2*2 + 1] + bz.y;
                if (MODE == 0) {
                    const int b_ = row >> 11, t_ = row & (TT - 1);
                    const size_t idx = ((size_t)(b_*HH + h)*TT + t_)*DD + d0;
                    if (which == 2) {
                        *(__half2*)(g_vf + idx) =
                            __half2(__float2half(vx), __float2half(vy));
                    } else {
                        __nv_bfloat16 hx = __float2bfloat16(vx);
                        __nv_bfloat16 hy = __float2bfloat16(vy);
                        *(__nv_bfloat162*)(dh + idx) = __nv_bfloat162(hx, hy);
                        *(__nv_bfloat162*)(dl + idx) = __nv_bfloat162(
                            __float2bfloat16(vx - __bfloat162float(hx)),
                            __float2bfloat16(vy - __bfloat162float(hy)));
                    }
                } else {
                    float2 v; v.x = vx; v.y = vy;
                    *(float2*)(out + (size_t)row * CC + gcol) = v;
                }
            }
        }
    }
}

// ---------------------------------------------------------------------------
// Tensor-core flash attention. q-tile 64, kv-tile 64, 4 warps, 2 CTA/SM.
// S = QhKh + QlKh + QhKl (bf16, 3-pass).
// O += Ph·Vf + Pl·Vf   (fp16: P split hi/lo, V single fp16 — 2-pass).
// KV stage: Kh(8K) Kl(8K) Vf(8K) = 24KB x 3 stages.
// ---------------------------------------------------------------------------
#define AQ_B    16384                  // Qh+Ql (8KB each)
#define KV_STG  24576
#define AT_SMEM (AQ_B + 3*KV_STG)      // 88 KB
#define NKT     (TT/64)                // 32

__global__ __launch_bounds__(128, 2)
void attn_mma_kernel()
{
    extern __shared__ __align__(128) char asm_[];
    const uint32_t sb = smem_u32(asm_);
    const uint32_t sQh = sb, sQl = sb + 8192, sKV = sb + AQ_B;

    const int tid = threadIdx.x;
    const int lane = tid & 31, w = tid >> 5;
    const int qb = blockIdx.x;          // 0..31
    const int bh = blockIdx.y;          // 0..63
    const int b_ = bh >> 4, h = bh & 15;

    const __nv_bfloat16* Qhg = g_qh + ((size_t)bh*TT + qb*64)*DD;
    const __nv_bfloat16* Qlg = g_ql + ((size_t)bh*TT + qb*64)*DD;
    const size_t kvb = (size_t)bh*TT*DD;

    const int ldRow = tid >> 1;
    const int ldS0  = (tid & 1) * 4;
    const uint32_t ldRowOff = (uint32_t)ldRow * 128;
    const uint32_t ldXor    = (uint32_t)(ldRow & 7);
    auto load_tile = [&](uint32_t dst, const void* srcv) {
        const char* g = (const char*)srcv + (size_t)ldRow * DD * 2 + ldS0*16;
        #pragma unroll
        for (int i = 0; i < 4; i++) {
            const uint32_t sw = (uint32_t)(((ldS0 + i) ^ ldXor) << 4);
            cp_async16(dst + ldRowOff + sw, g + i*16);
        }
    };
    auto issue_kv = [&](int kt) {
        if (kt < NKT) {
            const uint32_t st = sKV + (uint32_t)(kt % 3) * KV_STG;
            const size_t off = kvb + (size_t)kt*64*DD;
            load_tile(st,         g_kh + off);
            load_tile(st + 8192,  g_kl + off);
            load_tile(st + 16384, g_vf + off);
        }
        CP_COMMIT();
    };

    // prologue: group0 = Q + KV0; group1 = KV1  (2-deep, stages mod 3: safe)
    load_tile(sQh, Qhg);
    load_tile(sQl, Qlg);
    issue_kv(0);
    issue_kv(1);

    const uint32_t lx = (uint32_t)(lane & 7);

    uint32_t qhf[4][4], qlf[4][4];
    float o[8][4];
    #pragma unroll
    for (int nt = 0; nt < 8; nt++)
        #pragma unroll
        for (int r = 0; r < 4; r++) o[nt][r] = 0.f;
    float m0 = -1e30f, m1 = -1e30f, l0 = 0.f, l1 = 0.f;
    const float scale = 0.125f;

    for (int kt = 0; kt < NKT; kt++) {
        CP_WAIT1();
        __syncthreads();
        if (kt == 0) {
            const uint32_t qRowOff = (uint32_t)(w*16 + (lane & 15)) * 128;
            #pragma unroll
            for (int ks = 0; ks < 4; ks++) {
                const uint32_t off = (((uint32_t)(ks*2) + (lane >> 4)) ^ lx) << 4;
                ldmatrix_x4(qhf[ks], sQh + qRowOff + off);
                ldmatrix_x4(qlf[ks], sQl + qRowOff + off);
            }
        }
        issue_kv(kt + 2);

        const uint32_t st = sKV + (uint32_t)(kt % 3) * KV_STG;

        // ---- S = QhKh + QlKh + QhKl (bf16 3-pass) ----
        float s[8][4];
        #pragma unroll
        for (int nt = 0; nt < 8; nt++)
            #pragma unroll
            for (int r = 0; r < 4; r++) s[nt][r] = 0.f;

        const uint32_t kRowOff = (uint32_t)(lane & 15) * 128;
        #pragma unroll
        for (int ks = 0; ks < 4; ks++) {
            const uint32_t koff = (((uint32_t)(ks*2) + (lane >> 4)) ^ lx) << 4;
            uint32_t kf[4][4];
            #pragma unroll
            for (int p = 0; p < 4; p++)
                ldmatrix_x4(kf[p], st + (uint32_t)(p*2048) + kRowOff + koff);
            #pragma unroll
            for (int nt = 0; nt < 8; nt++) {
                const int p = nt >> 1, q = (nt & 1);
                mma_bf16(s[nt], qhf[ks], kf[p][q], kf[p][q + 2]);
            }
            #pragma unroll
            for (int nt = 0; nt < 8; nt++) {
                const int p = nt >> 1, q = (nt & 1);
                mma_bf16(s[nt], qlf[ks], kf[p][q], kf[p][q + 2]);
            }
            #pragma unroll
            for (int p = 0; p < 4; p++)
                ldmatrix_x4(kf[p], st + 8192 + (uint32_t)(p*2048) + kRowOff + koff);
            #pragma unroll
            for (int nt = 0; nt < 8; nt++) {
                const int p = nt >> 1, q = (nt & 1);
                mma_bf16(s[nt], qhf[ks], kf[p][q], kf[p][q + 2]);
            }
        }

        // ---- online softmax in fragments (rows lane>>2 and +8) ----
        float rm0 = -1e30f, rm1 = -1e30f;
        #pragma unroll
        for (int nt = 0; nt < 8; nt++) {
            #pragma unroll
            for (int r = 0; r < 4; r++) s[nt][r] *= scale;
            rm0 = fmaxf(rm0, fmaxf(s[nt][0], s[nt][1]));
            rm1 = fmaxf(rm1, fmaxf(s[nt][2], s[nt][3]));
        }
        rm0 = fmaxf(rm0, __shfl_xor_sync(0xffffffffu, rm0, 1));
        rm0 = fmaxf(rm0, __shfl_xor_sync(0xffffffffu, rm0, 2));
        rm1 = fmaxf(rm1, __shfl_xor_sync(0xffffffffu, rm1, 1));
        rm1 = fmaxf(rm1, __shfl_xor_sync(0xffffffffu, rm1, 2));
        const float mn0 = fmaxf(m0, rm0), mn1 = fmaxf(m1, rm1);
        const float al0 = __expf(m0 - mn0), al1 = __expf(m1 - mn1);
        m0 = mn0; m1 = mn1;

        uint32_t php[4][4], plp[4][4];
        float ls0 = 0.f, ls1 = 0.f;
        #pragma unroll
        for (int nt = 0; nt < 8; nt++) {
            float p0 = __expf(s[nt][0] - m0);
            float p1 = __expf(s[nt][1] - m0);
            float p2 = __expf(s[nt][2] - m1);
            float p3 = __expf(s[nt][3] - m1);
            ls0 += p0 + p1; ls1 += p2 + p3;
            __half h0 = __float2half(p0), h1 = __float2half(p1);
            __half h2 = __float2half(p2), h3 = __float2half(p3);
            const int kk = nt >> 1;
            __half2 hp01(h0, h1), hp23(h2, h3);
            php[kk][(nt&1)*2 + 0] = *(uint32_t*)&hp01;
            php[kk][(nt&1)*2 + 1] = *(uint32_t*)&hp23;
            plp[kk][(nt&1)*2 + 0] = packhf2(p0 - __half2float(h0),
                                            p1 - __half2float(h1));
            plp[kk][(nt&1)*2 + 1] = packhf2(p2 - __half2float(h2),
                                            p3 - __half2float(h3));
        }
        ls0 += __shfl_xor_sync(0xffffffffu, ls0, 1);
        ls0 += __shfl_xor_sync(0xffffffffu, ls0, 2);
        ls1 += __shfl_xor_sync(0xffffffffu, ls1, 1);
        ls1 += __shfl_xor_sync(0xffffffffu, ls1, 2);
        l0 = l0 * al0 + ls0;
        l1 = l1 * al1 + ls1;
        #pragma unroll
        for (int nt = 0; nt < 8; nt++) {
            o[nt][0] *= al0; o[nt][1] *= al0;
            o[nt][2] *= al1; o[nt][3] *= al1;
        }

        // ---- O += Ph·Vf + Pl·Vf  (fp16, 2 passes) ----
        const uint32_t vRow = (uint32_t)(((lane >> 3) & 1) * 8 + (lane & 7));
        #pragma unroll
        for (int kk = 0; kk < 4; kk++) {
            uint32_t vf[4][4];
            const uint32_t vrOff = ((uint32_t)(kk*16) + vRow) * 128;
            #pragma unroll
            for (int p = 0; p < 4; p++) {
                const uint32_t coff = (((uint32_t)(p*2) + (lane >> 4)) ^ lx) << 4;
                ldmatrix_x4t(vf[p], st + 16384 + vrOff + coff);
            }
            #pragma unroll
            for (int nt = 0; nt < 8; nt++) {
                const int p = nt >> 1, q = (nt & 1) * 2;
                mma_f16(o[nt], php[kk], vf[p][q], vf[p][q + 1]);
            }
            #pragma unroll
            for (int nt = 0; nt < 8; nt++) {
                const int p = nt >> 1, q = (nt & 1) * 2;
                mma_f16(o[nt], plp[kk], vf[p][q], vf[p][q + 1]);
            }
        }
    }

    // ---- epilogue: normalize, write single fp16 for the proj GEMM ----
    const float inv0 = 1.f / l0, inv1 = 1.f / l1;
    const int r0 = w*16 + (lane >> 2);
    const int t0 = qb*64 + r0;
    const size_t base0 = ((size_t)b_*TT + t0)*CC + h*64;
    const size_t base1 = base0 + 8*(size_t)CC;
    #pragma unroll
    for (int nt = 0; nt < 8; nt++) {
        const int col = nt*8 + (lane & 3)*2;
        float v0 = o[nt][0]*inv0, v1 = o[nt][1]*inv0;
        float v2 = o[nt][2]*inv1, v3 = o[nt][3]*inv1;
        *(__half2*)(g_a16 + base0 + col) =
            __half2(__float2half(v0), __float2half(v1));
        *(__half2*)(g_a16 + base1 + col) =
            __half2(__float2half(v2), __float2half(v3));
    }
}

// ---------------------------------------------------------------------------
extern "C" void kernel_launch(void* const* d_in, const int* in_sizes, int n_in,
                              void* d_out, int out_size)
{
    const float* x      = (const float*)d_in[0];
    const float* qkv_w  = (const float*)d_in[1];
    const float* qkv_b  = (const float*)d_in[2];
    const float* proj_w = (const float*)d_in[3];
    const float* proj_b = (const float*)d_in[4];
    float* out = (float*)d_out;
    (void)in_sizes; (void)n_in; (void)out_size;

    cudaFuncSetAttribute(mma_gemm<0>,
                         cudaFuncAttributeMaxDynamicSharedMemorySize, GSMEM);
    cudaFuncSetAttribute(mma_gemm<1>,
                         cudaFuncAttributeMaxDynamicSharedMemorySize, GSMEM);
    cudaFuncSetAttribute(attn_mma_kernel,
                         cudaFuncAttributeMaxDynamicSharedMemorySize, AT_SMEM);

    __nv_bfloat16 *xh, *xl, *wh, *wl;
    __half *p16h, *p16l, *a16;
    cudaGetSymbolAddress((void**)&xh, g_xh);
    cudaGetSymbolAddress((void**)&xl, g_xl);
    cudaGetSymbolAddress((void**)&wh, g_wh);
    cudaGetSymbolAddress((void**)&wl, g_wl);
    cudaGetSymbolAddress((void**)&p16h, g_p16h);
    cudaGetSymbolAddress((void**)&p16l, g_p16l);
    cudaGetSymbolAddress((void**)&a16, g_a16);

    // 1) operand prep
    split_f32_kernel<<<(BT_*CC/4 + 255)/256, 256>>>(x, xh, xl, BT_*CC/4);
    transpose_split_kernel<<<dim3(N3C/32, CC/32), dim3(32, 8)>>>(qkv_w, wh, wl, CC, N3C);
    transpose_split_f16_kernel<<<dim3(CC/32, CC/32), dim3(32, 8)>>>(proj_w, p16h, p16l, CC, CC);

    // 2) QKV GEMM (bf16 3-pass) -> Q/K bf16-split + V fp16
    mma_gemm<0><<<dim3(N3C/128, BT_/128), 256, GSMEM>>>(xh, xl, wh, wl, qkv_b, nullptr);

    // 3) tensor-core flash attention -> single-fp16 attention output
    attn_mma_kernel<<<dim3(TT/64, BB*HH), 128, AT_SMEM>>>();

    // 4) output projection (fp16 2-pass: A single, W split) -> d_out
    mma_gemm<1><<<dim3(CC/128, BT_/128), 256, GSMEM>>>(
        (const __nv_bfloat16*)a16, (const __nv_bfloat16*)a16,
        (const __nv_bfloat16*)p16h, (const __nv_bfloat16*)p16l, proj_b, out);
}

// round 14
// speedup vs baseline: 4.9331x; 1.3579x over previous
#include <cuda_runtime.h>
#include <cuda_bf16.h>
#include <cuda_fp16.h>
#include <cstdint>

#define BB 4
#define TT 2048
#define CC 1024
#define HH 16
#define DD 64
#define BT_ (BB*TT)      // 8192
#define N3C (3*CC)       // 3072
#define KK  1024

// ---------------------------------------------------------------------------
// Device scratch (all fp16 operand storage now)
// ---------------------------------------------------------------------------
__device__ __half g_q16h[BB*HH*TT*DD], g_q16l[BB*HH*TT*DD];  // Q fp16 hi/lo
__device__ __half g_k16[BB*HH*TT*DD];                        // K single fp16
__device__ __half g_vf[BB*HH*TT*DD];                         // V single fp16

__device__ __half g_x16[BT_*CC];                             // X single fp16
__device__ __half g_w16h[N3C*CC], g_w16l[N3C*CC];            // qkv_w^T fp16 hi/lo
__device__ __half g_p16h[CC*CC],  g_p16l[CC*CC];             // proj_w^T fp16 hi/lo
__device__ __half g_a16[BT_*CC];                             // attn out single fp16

// ---------------------------------------------------------------------------
// PTX helpers (plain sm_103-safe: ldmatrix/mma.sync/cp.async)
// ---------------------------------------------------------------------------
__device__ __forceinline__ uint32_t smem_u32(const void* p) {
    uint32_t a;
    asm("{ .reg .u64 t; cvta.to.shared.u64 t, %1; cvt.u32.u64 %0, t; }"
        : "=r"(a) : "l"(p));
    return a;
}
__device__ __forceinline__ void ldmatrix_x4(uint32_t* r, uint32_t addr) {
    asm volatile("ldmatrix.sync.aligned.m8n8.x4.shared.b16 {%0,%1,%2,%3}, [%4];"
                 : "=r"(r[0]), "=r"(r[1]), "=r"(r[2]), "=r"(r[3]) : "r"(addr));
}
__device__ __forceinline__ void ldmatrix_x4t(uint32_t* r, uint32_t addr) {
    asm volatile("ldmatrix.sync.aligned.m8n8.x4.trans.shared.b16 {%0,%1,%2,%3}, [%4];"
                 : "=r"(r[0]), "=r"(r[1]), "=r"(r[2]), "=r"(r[3]) : "r"(addr));
}
__device__ __forceinline__ void ldmatrix_x2(uint32_t* r, uint32_t addr) {
    asm volatile("ldmatrix.sync.aligned.m8n8.x2.shared.b16 {%0,%1}, [%2];"
                 : "=r"(r[0]), "=r"(r[1]) : "r"(addr));
}
__device__ __forceinline__ void mma_f16(float* d, const uint32_t* a,
                                        uint32_t b0, uint32_t b1) {
    asm volatile(
        "mma.sync.aligned.m16n8k16.row.col.f32.f16.f16.f32 "
        "{%0,%1,%2,%3}, {%4,%5,%6,%7}, {%8,%9}, {%0,%1,%2,%3};"
        : "+f"(d[0]), "+f"(d[1]), "+f"(d[2]), "+f"(d[3])
        : "r"(a[0]), "r"(a[1]), "r"(a[2]), "r"(a[3]), "r"(b0), "r"(b1));
}
__device__ __forceinline__ void cp_async16(uint32_t s, const void* g) {
    asm volatile("cp.async.cg.shared.global [%0], [%1], 16;"
                 :: "r"(s), "l"(g) : "memory");
}
#define CP_COMMIT() asm volatile("cp.async.commit_group;" ::: "memory")
#define CP_WAIT1()  asm volatile("cp.async.wait_group 1;" ::: "memory")

__device__ __forceinline__ uint32_t packhf2(float lo, float hi) {
    __half2 t(__float2half(lo), __float2half(hi));
    return *(uint32_t*)&t;
}

// ---------------------------------------------------------------------------
// Prep kernels
// ---------------------------------------------------------------------------
__global__ void convert_f16_kernel(const float* __restrict__ in,
                                   __half* __restrict__ out, int n4)
{
    int i = blockIdx.x * blockDim.x + threadIdx.x;
    if (i >= n4) return;
    float4 v = ((const float4*)in)[i];
    __half2* op = (__half2*)(out + i*4);
    op[0] = __half2(__float2half(v.x), __float2half(v.y));
    op[1] = __half2(__float2half(v.z), __float2half(v.w));
}

// in [R, C] f32 -> out [C, R] fp16 hi/lo (transpose + split)
__global__ void transpose_split_f16_kernel(const float* __restrict__ in,
                                           __half* __restrict__ hi,
                                           __half* __restrict__ lo,
                                           int R, int C)
{
    __shared__ float s[32][33];
    int c0 = blockIdx.x * 32, r0 = blockIdx.y * 32;
    int tx = threadIdx.x, ty = threadIdx.y;
    #pragma unroll
    for (int i = ty; i < 32; i += 8)
        s[i][tx] = in[(size_t)(r0 + i) * C + c0 + tx];
    __syncthreads();
    #pragma unroll
    for (int i = ty; i < 32; i += 8) {
        float v = s[tx][i];
        __half h = __float2half(v);
        size_t o = (size_t)(c0 + i) * R + r0 + tx;
        hi[o] = h;
        lo[o] = __float2half(v - __half2float(h));
    }
}

// ---------------------------------------------------------------------------
// Warp-MMA fp16 GEMM, 2-pass error-compensated: C = A·Bh + A·Bl.
// 128x128 tile, 8 warps, K-chunk 64, 3-stage cp.async, 2 CTA/SM.
// MODE 0: bias + scatter (Q fp16-split, K/V single fp16).  MODE 1: bias + f32.
// ---------------------------------------------------------------------------
#define KC       64
#define OPBYTES  16384
#define STG_B    (2*OPBYTES)
#define GSTAGES  3
#define GSMEM    (GSTAGES*STG_B)       // 96 KB
#define NCH      32                    // 2 passes x 16 chunks

template<int MODE>
__global__ __launch_bounds__(256, 2)
void mma_gemm(const __half* __restrict__ A,
              const __half* __restrict__ Bh, const __half* __restrict__ Bl,
              const float* __restrict__ bias, float* __restrict__ out)
{
    extern __shared__ __align__(128) char gsm[];
    const uint32_t sbase = smem_u32(gsm);

    const int tid  = threadIdx.x;
    const int lane = tid & 31, wid = tid >> 5;
    const int wr = wid >> 2, wc = wid & 3;
    const int bM = blockIdx.y * 128, bN = blockIdx.x * 128;

    const int ldRow = tid >> 1;
    const int ldS0  = (tid & 1) * 4;
    const uint32_t ldRowOff = (uint32_t)ldRow * 128;
    const uint32_t ldXor    = (uint32_t)(ldRow & 7);

    float acc[4][4][4];
    #pragma unroll
    for (int mt = 0; mt < 4; mt++)
        #pragma unroll
        for (int nt = 0; nt < 4; nt++)
            #pragma unroll
            for (int r = 0; r < 4; r++) acc[mt][nt][r] = 0.f;

    auto issue_chunk = [&](int g) {
        if (g < NCH) {
            const int pass = g >> 4;               // 0: A·Bh  1: A·Bl
            const int k0 = (g & 15) * KC;
            const __half* Bp = pass ? Bl : Bh;
            const uint32_t st = sbase + (uint32_t)(g % GSTAGES) * STG_B;
            const char* ga = (const char*)(A  + (size_t)(bM + ldRow) * KK + k0) + ldS0*16;
            const char* gb = (const char*)(Bp + (size_t)(bN + ldRow) * KK + k0) + ldS0*16;
            #pragma unroll
            for (int i = 0; i < 4; i++) {
                const uint32_t sw = (uint32_t)(((ldS0 + i) ^ ldXor) << 4);
                cp_async16(st + ldRowOff + sw,           ga + i*16);
                cp_async16(st + OPBYTES + ldRowOff + sw, gb + i*16);
            }
        }
        CP_COMMIT();
    };

    issue_chunk(0);
    issue_chunk(1);

    const uint32_t aRowOff = (uint32_t)(wr*64 + (lane & 15)) * 128;
    const uint32_t bRowOff = (uint32_t)(wc*32 + (lane & 7)) * 128;
    const uint32_t ahalf = (uint32_t)(lane >> 4);
    const uint32_t bhalf = (uint32_t)((lane >> 3) & 1);
    const uint32_t lx    = (uint32_t)(lane & 7);

    for (int c = 0; c < NCH; c++) {
        CP_WAIT1();
        __syncthreads();
        issue_chunk(c + 2);

        const uint32_t stA = sbase + (uint32_t)(c % GSTAGES) * STG_B;
        const uint32_t aB = stA + aRowOff;
        const uint32_t bB = stA + OPBYTES + bRowOff;

        #pragma unroll
        for (int ks = 0; ks < 4; ks++) {
            const uint32_t aoff = ((uint32_t)(ks*2) + ahalf ^ lx) << 4;
            const uint32_t boff = ((uint32_t)(ks*2) + bhalf ^ lx) << 4;
            uint32_t af[4][4], bf[4][2];
            #pragma unroll
            for (int mt = 0; mt < 4; mt++)
                ldmatrix_x4(af[mt], aB + (uint32_t)(mt*2048) + aoff);
            #pragma unroll
            for (int nt = 0; nt < 4; nt++)
                ldmatrix_x2(bf[nt], bB + (uint32_t)(nt*1024) + boff);
            #pragma unroll
            for (int mt = 0; mt < 4; mt++)
                #pragma unroll
                for (int nt = 0; nt < 4; nt++)
                    mma_f16(acc[mt][nt], af[mt], bf[nt][0], bf[nt][1]);
        }
    }

    const int mrow0 = bM + wr*64 + (lane >> 2);
    #pragma unroll
    for (int nt = 0; nt < 4; nt++) {
        const int gcol = bN + wc*32 + nt*8 + (lane & 3)*2;
        const float2 bz = *(const float2*)(bias + gcol);
        int which = 0, h = 0, d0 = 0;
        if (MODE == 0) {
            which = gcol >> 10;                    // 0=Q, 1=K, 2=V
            const int rem = gcol & 1023;
            h = rem >> 6; d0 = rem & 63;
        }
        #pragma unroll
        for (int mt = 0; mt < 4; mt++) {
            #pragma unroll
            for (int h2 = 0; h2 < 2; h2++) {
                const int row = mrow0 + mt*16 + h2*8;
                float vx = acc[mt][nt][h2*2 + 0] + bz.x;
                float vy = acc[mt][nt][h2*2 + 1] + bz.y;
                if (MODE == 0) {
                    const int b_ = row >> 11, t_ = row & (TT - 1);
                    const size_t idx = ((size_t)(b_*HH + h)*TT + t_)*DD + d0;
                    if (which == 0) {
                        __half hx = __float2half(vx);
                        __half hy = __float2half(vy);
                        *(__half2*)(g_q16h + idx) = __half2(hx, hy);
                        *(__half2*)(g_q16l + idx) = __half2(
                            __float2half(vx - __half2float(hx)),
                            __float2half(vy - __half2float(hy)));
                    } else {
                        __half* dst = (which == 1) ? g_k16 : g_vf;
                        *(__half2*)(dst + idx) =
                            __half2(__float2half(vx), __float2half(vy));
                    }
                } else {
                    float2 v; v.x = vx; v.y = vy;
                    *(float2*)(out + (size_t)row * CC + gcol) = v;
                }
            }
        }
    }
}

// ---------------------------------------------------------------------------
// Tensor-core flash attention. q-tile 64, kv-tile 64, 4 warps, 2 CTA/SM.
// S = (Qh+Ql)·K16   (fp16 2-pass, Q split / K single).
// O += Ph·Vf + Pl·Vf (fp16 2-pass, P split / V single).
// KV stage: K16(8K) Vf(8K) = 16KB x 3 stages; Q 16KB -> 64 KB total.
// ---------------------------------------------------------------------------
#define AQ_B    16384                  // Qh+Ql (8KB each)
#define KV_STG  16384
#define AT_SMEM (AQ_B + 3*KV_STG)      // 64 KB
#define NKT     (TT/64)                // 32

__global__ __launch_bounds__(128, 2)
void attn_mma_kernel()
{
    extern __shared__ __align__(128) char asm_[];
    const uint32_t sb = smem_u32(asm_);
    const uint32_t sQh = sb, sQl = sb + 8192, sKV = sb + AQ_B;

    const int tid = threadIdx.x;
    const int lane = tid & 31, w = tid >> 5;
    const int qb = blockIdx.x;          // 0..31
    const int bh = blockIdx.y;          // 0..63
    const int b_ = bh >> 4, h = bh & 15;

    const __half* Qhg = g_q16h + ((size_t)bh*TT + qb*64)*DD;
    const __half* Qlg = g_q16l + ((size_t)bh*TT + qb*64)*DD;
    const size_t kvb = (size_t)bh*TT*DD;

    const int ldRow = tid >> 1;
    const int ldS0  = (tid & 1) * 4;
    const uint32_t ldRowOff = (uint32_t)ldRow * 128;
    const uint32_t ldXor    = (uint32_t)(ldRow & 7);
    auto load_tile = [&](uint32_t dst, const void* srcv) {
        const char* g = (const char*)srcv + (size_t)ldRow * DD * 2 + ldS0*16;
        #pragma unroll
        for (int i = 0; i < 4; i++) {
            const uint32_t sw = (uint32_t)(((ldS0 + i) ^ ldXor) << 4);
            cp_async16(dst + ldRowOff + sw, g + i*16);
        }
    };
    auto issue_kv = [&](int kt) {
        if (kt < NKT) {
            const uint32_t st = sKV + (uint32_t)(kt % 3) * KV_STG;
            const size_t off = kvb + (size_t)kt*64*DD;
            load_tile(st,        g_k16 + off);
            load_tile(st + 8192, g_vf + off);
        }
        CP_COMMIT();
    };

    // prologue: group0 = Q + KV0; group1 = KV1  (2-deep over 3 stages: safe)
    load_tile(sQh, Qhg);
    load_tile(sQl, Qlg);
    issue_kv(0);
    issue_kv(1);

    const uint32_t lx = (uint32_t)(lane & 7);

    uint32_t qhf[4][4], qlf[4][4];
    float o[8][4];
    #pragma unroll
    for (int nt = 0; nt < 8; nt++)
        #pragma unroll
        for (int r = 0; r < 4; r++) o[nt][r] = 0.f;
    float m0 = -1e30f, m1 = -1e30f, l0 = 0.f, l1 = 0.f;
    const float scale = 0.125f;

    for (int kt = 0; kt < NKT; kt++) {
        CP_WAIT1();
        __syncthreads();
        if (kt == 0) {
            const uint32_t qRowOff = (uint32_t)(w*16 + (lane & 15)) * 128;
            #pragma unroll
            for (int ks = 0; ks < 4; ks++) {
                const uint32_t off = (((uint32_t)(ks*2) + (lane >> 4)) ^ lx) << 4;
                ldmatrix_x4(qhf[ks], sQh + qRowOff + off);
                ldmatrix_x4(qlf[ks], sQl + qRowOff + off);
            }
        }
        issue_kv(kt + 2);

        const uint32_t st = sKV + (uint32_t)(kt % 3) * KV_STG;

        // ---- S = (Qh+Ql)·K16 (fp16 2-pass) ----
        float s[8][4];
        #pragma unroll
        for (int nt = 0; nt < 8; nt++)
            #pragma unroll
            for (int r = 0; r < 4; r++) s[nt][r] = 0.f;

        const uint32_t kRowOff = (uint32_t)(lane & 15) * 128;
        #pragma unroll
        for (int ks = 0; ks < 4; ks++) {
            const uint32_t koff = (((uint32_t)(ks*2) + (lane >> 4)) ^ lx) << 4;
            uint32_t kf[4][4];
            #pragma unroll
            for (int p = 0; p < 4; p++)
                ldmatrix_x4(kf[p], st + (uint32_t)(p*2048) + kRowOff + koff);
            #pragma unroll
            for (int nt = 0; nt < 8; nt++) {
                const int p = nt >> 1, q = (nt & 1);
                mma_f16(s[nt], qhf[ks], kf[p][q], kf[p][q + 2]);
            }
            #pragma unroll
            for (int nt = 0; nt < 8; nt++) {
                const int p = nt >> 1, q = (nt & 1);
                mma_f16(s[nt], qlf[ks], kf[p][q], kf[p][q + 2]);
            }
        }

        // ---- online softmax in fragments (rows lane>>2 and +8) ----
        float rm0 = -1e30f, rm1 = -1e30f;
        #pragma unroll
        for (int nt = 0; nt < 8; nt++) {
            #pragma unroll
            for (int r = 0; r < 4; r++) s[nt][r] *= scale;
            rm0 = fmaxf(rm0, fmaxf(s[nt][0], s[nt][1]));
            rm1 = fmaxf(rm1, fmaxf(s[nt][2], s[nt][3]));
        }
        rm0 = fmaxf(rm0, __shfl_xor_sync(0xffffffffu, rm0, 1));
        rm0 = fmaxf(rm0, __shfl_xor_sync(0xffffffffu, rm0, 2));
        rm1 = fmaxf(rm1, __shfl_xor_sync(0xffffffffu, rm1, 1));
        rm1 = fmaxf(rm1, __shfl_xor_sync(0xffffffffu, rm1, 2));
        const float mn0 = fmaxf(m0, rm0), mn1 = fmaxf(m1, rm1);
        const float al0 = __expf(m0 - mn0), al1 = __expf(m1 - mn1);
        m0 = mn0; m1 = mn1;

        uint32_t php[4][4], plp[4][4];
        float ls0 = 0.f, ls1 = 0.f;
        #pragma unroll
        for (int nt = 0; nt < 8; nt++) {
            float p0 = __expf(s[nt][0] - m0);
            float p1 = __expf(s[nt][1] - m0);
            float p2 = __expf(s[nt][2] - m1);
            float p3 = __expf(s[nt][3] - m1);
            ls0 += p0 + p1; ls1 += p2 + p3;
            __half h0 = __float2half(p0), h1 = __float2half(p1);
            __half h2 = __float2half(p2), h3 = __float2half(p3);
            const int kk = nt >> 1;
            __half2 hp01(h0, h1), hp23(h2, h3);
            php[kk][(nt&1)*2 + 0] = *(uint32_t*)&hp01;
            php[kk][(nt&1)*2 + 1] = *(uint32_t*)&hp23;
            plp[kk][(nt&1)*2 + 0] = packhf2(p0 - __half2float(h0),
                                            p1 - __half2float(h1));
            plp[kk][(nt&1)*2 + 1] = packhf2(p2 - __half2float(h2),
                                            p3 - __half2float(h3));
        }
        ls0 += __shfl_xor_sync(0xffffffffu, ls0, 1);
        ls0 += __shfl_xor_sync(0xffffffffu, ls0, 2);
        ls1 += __shfl_xor_sync(0xffffffffu, ls1, 1);
        ls1 += __shfl_xor_sync(0xffffffffu, ls1, 2);
        l0 = l0 * al0 + ls0;
        l1 = l1 * al1 + ls1;
        #pragma unroll
        for (int nt = 0; nt < 8; nt++) {
            o[nt][0] *= al0; o[nt][1] *= al0;
            o[nt][2] *= al1; o[nt][3] *= al1;
        }

        // ---- O += Ph·Vf + Pl·Vf  (fp16 2-pass) ----
        const uint32_t vRow = (uint32_t)(((lane >> 3) & 1) * 8 + (lane & 7));
        #pragma unroll
        for (int kk = 0; kk < 4; kk++) {
            uint32_t vf[4][4];
            const uint32_t vrOff = ((uint32_t)(kk*16) + vRow) * 128;
            #pragma unroll
            for (int p = 0; p < 4; p++) {
                const uint32_t coff = (((uint32_t)(p*2) + (lane >> 4)) ^ lx) << 4;
                ldmatrix_x4t(vf[p], st + 8192 + vrOff + coff);
            }
            #pragma unroll
            for (int nt = 0; nt < 8; nt++) {
                const int p = nt >> 1, q = (nt & 1) * 2;
                mma_f16(o[nt], php[kk], vf[p][q], vf[p][q + 1]);
            }
            #pragma unroll
            for (int nt = 0; nt < 8; nt++) {
                const int p = nt >> 1, q = (nt & 1) * 2;
                mma_f16(o[nt], plp[kk], vf[p][q], vf[p][q + 1]);
            }
        }
    }

    // ---- epilogue: normalize, write single fp16 for the proj GEMM ----
    const float inv0 = 1.f / l0, inv1 = 1.f / l1;
    const int r0 = w*16 + (lane >> 2);
    const int t0 = qb*64 + r0;
    const size_t base0 = ((size_t)b_*TT + t0)*CC + h*64;
    const size_t base1 = base0 + 8*(size_t)CC;
    #pragma unroll
    for (int nt = 0; nt < 8; nt++) {
        const int col = nt*8 + (lane & 3)*2;
        float v0 = o[nt][0]*inv0, v1 = o[nt][1]*inv0;
        float v2 = o[nt][2]*inv1, v3 = o[nt][3]*inv1;
        *(__half2*)(g_a16 + base0 + col) =
            __half2(__float2half(v0), __float2half(v1));
        *(__half2*)(g_a16 + base1 + col) =
            __half2(__float2half(v2), __float2half(v3));
    }
}

// ---------------------------------------------------------------------------
extern "C" void kernel_launch(void* const* d_in, const int* in_sizes, int n_in,
                              void* d_out, int out_size)
{
    const float* x      = (const float*)d_in[0];
    const float* qkv_w  = (const float*)d_in[1];
    const float* qkv_b  = (const float*)d_in[2];
    const float* proj_w = (const float*)d_in[3];
    const float* proj_b = (const float*)d_in[4];
    float* out = (float*)d_out;
    (void)in_sizes; (void)n_in; (void)out_size;

    cudaFuncSetAttribute(mma_gemm<0>,
                         cudaFuncAttributeMaxDynamicSharedMemorySize, GSMEM);
    cudaFuncSetAttribute(mma_gemm<1>,
                         cudaFuncAttributeMaxDynamicSharedMemorySize, GSMEM);
    cudaFuncSetAttribute(attn_mma_kernel,
                         cudaFuncAttributeMaxDynamicSharedMemorySize, AT_SMEM);

    __half *x16, *w16h, *w16l, *p16h, *p16l, *a16;
    cudaGetSymbolAddress((void**)&x16, g_x16);
    cudaGetSymbolAddress((void**)&w16h, g_w16h);
    cudaGetSymbolAddress((void**)&w16l, g_w16l);
    cudaGetSymbolAddress((void**)&p16h, g_p16h);
    cudaGetSymbolAddress((void**)&p16l, g_p16l);
    cudaGetSymbolAddress((void**)&a16, g_a16);

    // 1) operand prep
    convert_f16_kernel<<<(BT_*CC/4 + 255)/256, 256>>>(x, x16, BT_*CC/4);
    transpose_split_f16_kernel<<<dim3(N3C/32, CC/32), dim3(32, 8)>>>(qkv_w, w16h, w16l, CC, N3C);
    transpose_split_f16_kernel<<<dim3(CC/32, CC/32), dim3(32, 8)>>>(proj_w, p16h, p16l, CC, CC);

    // 2) QKV GEMM (fp16 2-pass) -> Q fp16-split, K/V single fp16
    mma_gemm<0><<<dim3(N3C/128, BT_/128), 256, GSMEM>>>(x16, w16h, w16l, qkv_b, nullptr);

    // 3) tensor-core flash attention -> single-fp16 attention output
    attn_mma_kernel<<<dim3(TT/64, BB*HH), 128, AT_SMEM>>>();

    // 4) output projection (fp16 2-pass) -> d_out
    mma_gemm<1><<<dim3(CC/128, BT_/128), 256, GSMEM>>>(a16, p16h, p16l, proj_b, out);
}

// round 16
// speedup vs baseline: 8.1712x; 1.6564x over previous
#include <cuda_runtime.h>
#include <cuda_fp16.h>
#include <cstdint>

#define BB 4
#define TT 2048
#define CC 1024
#define HH 16
#define DD 64
#define BT_ (BB*TT)      // 8192
#define N3C (3*CC)       // 3072
#define KK  1024

// ---------------------------------------------------------------------------
// Device scratch (single fp16 everywhere)
// ---------------------------------------------------------------------------
__device__ __half g_q16[BB*HH*TT*DD];     // Q fp16 [B,H,T,D]
__device__ __half g_k16[BB*HH*TT*DD];     // K fp16
__device__ __half g_vf[BB*HH*TT*DD];      // V fp16

__device__ __half g_x16[BT_*CC];          // X fp16 [M,K]
__device__ __half g_w16[N3C*CC];          // qkv_w^T fp16 [N,K]
__device__ __half g_p16[CC*CC];           // proj_w^T fp16 [N,K]
__device__ __half g_a16[BT_*CC];          // attn out fp16 [M,K]

// ---------------------------------------------------------------------------
// PTX helpers (plain sm_103-safe: ldmatrix/mma.sync/cp.async)
// ---------------------------------------------------------------------------
__device__ __forceinline__ uint32_t smem_u32(const void* p) {
    uint32_t a;
    asm("{ .reg .u64 t; cvta.to.shared.u64 t, %1; cvt.u32.u64 %0, t; }"
        : "=r"(a) : "l"(p));
    return a;
}
__device__ __forceinline__ void ldmatrix_x4(uint32_t* r, uint32_t addr) {
    asm volatile("ldmatrix.sync.aligned.m8n8.x4.shared.b16 {%0,%1,%2,%3}, [%4];"
                 : "=r"(r[0]), "=r"(r[1]), "=r"(r[2]), "=r"(r[3]) : "r"(addr));
}
__device__ __forceinline__ void ldmatrix_x4t(uint32_t* r, uint32_t addr) {
    asm volatile("ldmatrix.sync.aligned.m8n8.x4.trans.shared.b16 {%0,%1,%2,%3}, [%4];"
                 : "=r"(r[0]), "=r"(r[1]), "=r"(r[2]), "=r"(r[3]) : "r"(addr));
}
__device__ __forceinline__ void ldmatrix_x2(uint32_t* r, uint32_t addr) {
    asm volatile("ldmatrix.sync.aligned.m8n8.x2.shared.b16 {%0,%1}, [%2];"
                 : "=r"(r[0]), "=r"(r[1]) : "r"(addr));
}
__device__ __forceinline__ void mma_f16(float* d, const uint32_t* a,
                                        uint32_t b0, uint32_t b1) {
    asm volatile(
        "mma.sync.aligned.m16n8k16.row.col.f32.f16.f16.f32 "
        "{%0,%1,%2,%3}, {%4,%5,%6,%7}, {%8,%9}, {%0,%1,%2,%3};"
        : "+f"(d[0]), "+f"(d[1]), "+f"(d[2]), "+f"(d[3])
        : "r"(a[0]), "r"(a[1]), "r"(a[2]), "r"(a[3]), "r"(b0), "r"(b1));
}
__device__ __forceinline__ void cp_async16(uint32_t s, const void* g) {
    asm volatile("cp.async.cg.shared.global [%0], [%1], 16;"
                 :: "r"(s), "l"(g) : "memory");
}
#define CP_COMMIT() asm volatile("cp.async.commit_group;" ::: "memory")
#define CP_WAIT1()  asm volatile("cp.async.wait_group 1;" ::: "memory")

// ---------------------------------------------------------------------------
// Prep kernels
// ---------------------------------------------------------------------------
__global__ void convert_f16_kernel(const float* __restrict__ in,
                                   __half* __restrict__ out, int n4)
{
    int i = blockIdx.x * blockDim.x + threadIdx.x;
    if (i >= n4) return;
    float4 v = ((const float4*)in)[i];
    __half2* op = (__half2*)(out + i*4);
    op[0] = __half2(__float2half(v.x), __float2half(v.y));
    op[1] = __half2(__float2half(v.z), __float2half(v.w));
}

// in [R, C] f32 -> out [C, R] fp16 (transpose + convert)
__global__ void transpose_f16_kernel(const float* __restrict__ in,
                                     __half* __restrict__ out,
                                     int R, int C)
{
    __shared__ float s[32][33];
    int c0 = blockIdx.x * 32, r0 = blockIdx.y * 32;
    int tx = threadIdx.x, ty = threadIdx.y;
    #pragma unroll
    for (int i = ty; i < 32; i += 8)
        s[i][tx] = in[(size_t)(r0 + i) * C + c0 + tx];
    __syncthreads();
    #pragma unroll
    for (int i = ty; i < 32; i += 8)
        out[(size_t)(c0 + i) * R + r0 + tx] = __float2half(s[tx][i]);
}

// ---------------------------------------------------------------------------
// Warp-MMA fp16 GEMM, single pass: C = A·B.
// 128x128 tile, 8 warps, K-chunk 64, 3-stage cp.async, 2 CTA/SM.
// MODE 0: bias + scatter to g_q16/g_k16/g_vf [B,H,T,D].  MODE 1: bias + f32.
// ---------------------------------------------------------------------------
#define KC       64
#define OPBYTES  16384
#define STG_B    (2*OPBYTES)
#define GSTAGES  3
#define GSMEM    (GSTAGES*STG_B)       // 96 KB
#define NCH      16                    // single pass x 16 chunks

template<int MODE>
__global__ __launch_bounds__(256, 2)
void mma_gemm(const __half* __restrict__ A, const __half* __restrict__ B,
              const float* __restrict__ bias, float* __restrict__ out)
{
    extern __shared__ __align__(128) char gsm[];
    const uint32_t sbase = smem_u32(gsm);

    const int tid  = threadIdx.x;
    const int lane = tid & 31, wid = tid >> 5;
    const int wr = wid >> 2, wc = wid & 3;
    const int bM = blockIdx.y * 128, bN = blockIdx.x * 128;

    const int ldRow = tid >> 1;
    const int ldS0  = (tid & 1) * 4;
    const uint32_t ldRowOff = (uint32_t)ldRow * 128;
    const uint32_t ldXor    = (uint32_t)(ldRow & 7);

    float acc[4][4][4];
    #pragma unroll
    for (int mt = 0; mt < 4; mt++)
        #pragma unroll
        for (int nt = 0; nt < 4; nt++)
            #pragma unroll
            for (int r = 0; r < 4; r++) acc[mt][nt][r] = 0.f;

    auto issue_chunk = [&](int g) {
        if (g < NCH) {
            const int k0 = g * KC;
            const uint32_t st = sbase + (uint32_t)(g % GSTAGES) * STG_B;
            const char* ga = (const char*)(A + (size_t)(bM + ldRow) * KK + k0) + ldS0*16;
            const char* gb = (const char*)(B + (size_t)(bN + ldRow) * KK + k0) + ldS0*16;
            #pragma unroll
            for (int i = 0; i < 4; i++) {
                const uint32_t sw = (uint32_t)(((ldS0 + i) ^ ldXor) << 4);
                cp_async16(st + ldRowOff + sw,           ga + i*16);
                cp_async16(st + OPBYTES + ldRowOff + sw, gb + i*16);
            }
        }
        CP_COMMIT();
    };

    issue_chunk(0);
    issue_chunk(1);

    const uint32_t aRowOff = (uint32_t)(wr*64 + (lane & 15)) * 128;
    const uint32_t bRowOff = (uint32_t)(wc*32 + (lane & 7)) * 128;
    const uint32_t ahalf = (uint32_t)(lane >> 4);
    const uint32_t bhalf = (uint32_t)((lane >> 3) & 1);
    const uint32_t lx    = (uint32_t)(lane & 7);

    for (int c = 0; c < NCH; c++) {
        CP_WAIT1();
        __syncthreads();
        issue_chunk(c + 2);

        const uint32_t stA = sbase + (uint32_t)(c % GSTAGES) * STG_B;
        const uint32_t aB = stA + aRowOff;
        const uint32_t bB = stA + OPBYTES + bRowOff;

        #pragma unroll
        for (int ks = 0; ks < 4; ks++) {
            const uint32_t aoff = ((uint32_t)(ks*2) + ahalf ^ lx) << 4;
            const uint32_t boff = ((uint32_t)(ks*2) + bhalf ^ lx) << 4;
            uint32_t af[4][4], bf[4][2];
            #pragma unroll
            for (int mt = 0; mt < 4; mt++)
                ldmatrix_x4(af[mt], aB + (uint32_t)(mt*2048) + aoff);
            #pragma unroll
            for (int nt = 0; nt < 4; nt++)
                ldmatrix_x2(bf[nt], bB + (uint32_t)(nt*1024) + boff);
            #pragma unroll
            for (int mt = 0; mt < 4; mt++)
                #pragma unroll
                for (int nt = 0; nt < 4; nt++)
                    mma_f16(acc[mt][nt], af[mt], bf[nt][0], bf[nt][1]);
        }
    }

    const int mrow0 = bM + wr*64 + (lane >> 2);
    #pragma unroll
    for (int nt = 0; nt < 4; nt++) {
        const int gcol = bN + wc*32 + nt*8 + (lane & 3)*2;
        const float2 bz = *(const float2*)(bias + gcol);
        __half* dst = nullptr;
        int h = 0, d0 = 0;
        if (MODE == 0) {
            const int which = gcol >> 10;          // 0=Q, 1=K, 2=V
            const int rem = gcol & 1023;
            h = rem >> 6; d0 = rem & 63;
            dst = (which == 0) ? g_q16 : (which == 1 ? g_k16 : g_vf);
        }
        #pragma unroll
        for (int mt = 0; mt < 4; mt++) {
            #pragma unroll
            for (int h2 = 0; h2 < 2; h2++) {
                const int row = mrow0 + mt*16 + h2*8;
                float vx = acc[mt][nt][h2*2 + 0] + bz.x;
                float vy = acc[mt][nt][h2*2 + 1] + bz.y;
                if (MODE == 0) {
                    const int b_ = row >> 11, t_ = row & (TT - 1);
                    const size_t idx = ((size_t)(b_*HH + h)*TT + t_)*DD + d0;
                    *(__half2*)(dst + idx) =
                        __half2(__float2half(vx), __float2half(vy));
                } else {
                    float2 v; v.x = vx; v.y = vy;
                    *(float2*)(out + (size_t)row * CC + gcol) = v;
                }
            }
        }
    }
}

// ---------------------------------------------------------------------------
// Tensor-core flash attention, all single-pass fp16.
// q-tile 64, kv-tile 64, 4 warps, 2 CTA/SM.
// S = Q·K  (1 pass);  O += P·V  (1 pass).
// Smem: Q 8KB + 3 stages x (K 8KB + V 8KB) = 56 KB.
// ---------------------------------------------------------------------------
#define AQ_B    8192
#define KV_STG  16384
#define AT_SMEM (AQ_B + 3*KV_STG)      // 56 KB
#define NKT     (TT/64)                // 32

__global__ __launch_bounds__(128, 2)
void attn_mma_kernel()
{
    extern __shared__ __align__(128) char asm_[];
    const uint32_t sb = smem_u32(asm_);
    const uint32_t sQ = sb, sKV = sb + AQ_B;

    const int tid = threadIdx.x;
    const int lane = tid & 31, w = tid >> 5;
    const int qb = blockIdx.x;          // 0..31
    const int bh = blockIdx.y;          // 0..63
    const int b_ = bh >> 4, h = bh & 15;

    const __half* Qg = g_q16 + ((size_t)bh*TT + qb*64)*DD;
    const size_t kvb = (size_t)bh*TT*DD;

    const int ldRow = tid >> 1;
    const int ldS0  = (tid & 1) * 4;
    const uint32_t ldRowOff = (uint32_t)ldRow * 128;
    const uint32_t ldXor    = (uint32_t)(ldRow & 7);
    auto load_tile = [&](uint32_t dst, const void* srcv) {
        const char* g = (const char*)srcv + (size_t)ldRow * DD * 2 + ldS0*16;
        #pragma unroll
        for (int i = 0; i < 4; i++) {
            const uint32_t sw = (uint32_t)(((ldS0 + i) ^ ldXor) << 4);
            cp_async16(dst + ldRowOff + sw, g + i*16);
        }
    };
    auto issue_kv = [&](int kt) {
        if (kt < NKT) {
            const uint32_t st = sKV + (uint32_t)(kt % 3) * KV_STG;
            const size_t off = kvb + (size_t)kt*64*DD;
            load_tile(st,        g_k16 + off);
            load_tile(st + 8192, g_vf + off);
        }
        CP_COMMIT();
    };

    // prologue: group0 = Q + KV0; group1 = KV1  (2-deep over 3 stages: safe)
    load_tile(sQ, Qg);
    issue_kv(0);
    issue_kv(1);

    const uint32_t lx = (uint32_t)(lane & 7);

    uint32_t qf[4][4];
    float o[8][4];
    #pragma unroll
    for (int nt = 0; nt < 8; nt++)
        #pragma unroll
        for (int r = 0; r < 4; r++) o[nt][r] = 0.f;
    float m0 = -1e30f, m1 = -1e30f, l0 = 0.f, l1 = 0.f;
    const float scale = 0.125f;

    for (int kt = 0; kt < NKT; kt++) {
        CP_WAIT1();
        __syncthreads();
        if (kt == 0) {
            const uint32_t qRowOff = (uint32_t)(w*16 + (lane & 15)) * 128;
            #pragma unroll
            for (int ks = 0; ks < 4; ks++) {
                const uint32_t off = (((uint32_t)(ks*2) + (lane >> 4)) ^ lx) << 4;
                ldmatrix_x4(qf[ks], sQ + qRowOff + off);
            }
        }
        issue_kv(kt + 2);

        const uint32_t st = sKV + (uint32_t)(kt % 3) * KV_STG;

        // ---- S = Q·K (single pass) ----
        float s[8][4];
        #pragma unroll
        for (int nt = 0; nt < 8; nt++)
            #pragma unroll
            for (int r = 0; r < 4; r++) s[nt][r] = 0.f;

        const uint32_t kRowOff = (uint32_t)(lane & 15) * 128;
        #pragma unroll
        for (int ks = 0; ks < 4; ks++) {
            const uint32_t koff = (((uint32_t)(ks*2) + (lane >> 4)) ^ lx) << 4;
            uint32_t kf[4][4];
            #pragma unroll
            for (int p = 0; p < 4; p++)
                ldmatrix_x4(kf[p], st + (uint32_t)(p*2048) + kRowOff + koff);
            #pragma unroll
            for (int nt = 0; nt < 8; nt++) {
                const int p = nt >> 1, q = (nt & 1);
                mma_f16(s[nt], qf[ks], kf[p][q], kf[p][q + 2]);
            }
        }

        // ---- online softmax in fragments (rows lane>>2 and +8) ----
        float rm0 = -1e30f, rm1 = -1e30f;
        #pragma unroll
        for (int nt = 0; nt < 8; nt++) {
            #pragma unroll
            for (int r = 0; r < 4; r++) s[nt][r] *= scale;
            rm0 = fmaxf(rm0, fmaxf(s[nt][0], s[nt][1]));
            rm1 = fmaxf(rm1, fmaxf(s[nt][2], s[nt][3]));
        }
        rm0 = fmaxf(rm0, __shfl_xor_sync(0xffffffffu, rm0, 1));
        rm0 = fmaxf(rm0, __shfl_xor_sync(0xffffffffu, rm0, 2));
        rm1 = fmaxf(rm1, __shfl_xor_sync(0xffffffffu, rm1, 1));
        rm1 = fmaxf(rm1, __shfl_xor_sync(0xffffffffu, rm1, 2));
        const float mn0 = fmaxf(m0, rm0), mn1 = fmaxf(m1, rm1);
        const float al0 = __expf(m0 - mn0), al1 = __expf(m1 - mn1);
        m0 = mn0; m1 = mn1;

        uint32_t php[4][4];
        float ls0 = 0.f, ls1 = 0.f;
        #pragma unroll
        for (int nt = 0; nt < 8; nt++) {
            float p0 = __expf(s[nt][0] - m0);
            float p1 = __expf(s[nt][1] - m0);
            float p2 = __expf(s[nt][2] - m1);
            float p3 = __expf(s[nt][3] - m1);
            ls0 += p0 + p1; ls1 += p2 + p3;
            const int kk = nt >> 1;
            __half2 hp01(__float2half(p0), __float2half(p1));
            __half2 hp23(__float2half(p2), __float2half(p3));
            php[kk][(nt&1)*2 + 0] = *(uint32_t*)&hp01;
            php[kk][(nt&1)*2 + 1] = *(uint32_t*)&hp23;
        }
        ls0 += __shfl_xor_sync(0xffffffffu, ls0, 1);
        ls0 += __shfl_xor_sync(0xffffffffu, ls0, 2);
        ls1 += __shfl_xor_sync(0xffffffffu, ls1, 1);
        ls1 += __shfl_xor_sync(0xffffffffu, ls1, 2);
        l0 = l0 * al0 + ls0;
        l1 = l1 * al1 + ls1;
        #pragma unroll
        for (int nt = 0; nt < 8; nt++) {
            o[nt][0] *= al0; o[nt][1] *= al0;
            o[nt][2] *= al1; o[nt][3] *= al1;
        }

        // ---- O += P·V (single pass) ----
        const uint32_t vRow = (uint32_t)(((lane >> 3) & 1) * 8 + (lane & 7));
        #pragma unroll
        for (int kk = 0; kk < 4; kk++) {
            uint32_t vf[4][4];
            const uint32_t vrOff = ((uint32_t)(kk*16) + vRow) * 128;
            #pragma unroll
            for (int p = 0; p < 4; p++) {
                const uint32_t coff = (((uint32_t)(p*2) + (lane >> 4)) ^ lx) << 4;
                ldmatrix_x4t(vf[p], st + 8192 + vrOff + coff);
            }
            #pragma unroll
            for (int nt = 0; nt < 8; nt++) {
                const int p = nt >> 1, q = (nt & 1) * 2;
                mma_f16(o[nt], php[kk], vf[p][q], vf[p][q + 1]);
            }
        }
    }

    // ---- epilogue: normalize, write single fp16 for the proj GEMM ----
    const float inv0 = 1.f / l0, inv1 = 1.f / l1;
    const int r0 = w*16 + (lane >> 2);
    const int t0 = qb*64 + r0;
    const size_t base0 = ((size_t)b_*TT + t0)*CC + h*64;
    const size_t base1 = base0 + 8*(size_t)CC;
    #pragma unroll
    for (int nt = 0; nt < 8; nt++) {
        const int col = nt*8 + (lane & 3)*2;
        float v0 = o[nt][0]*inv0, v1 = o[nt][1]*inv0;
        float v2 = o[nt][2]*inv1, v3 = o[nt][3]*inv1;
        *(__half2*)(g_a16 + base0 + col) =
            __half2(__float2half(v0), __float2half(v1));
        *(__half2*)(g_a16 + base1 + col) =
            __half2(__float2half(v2), __float2half(v3));
    }
}

// ---------------------------------------------------------------------------
extern "C" void kernel_launch(void* const* d_in, const int* in_sizes, int n_in,
                              void* d_out, int out_size)
{
    const float* x      = (const float*)d_in[0];
    const float* qkv_w  = (const float*)d_in[1];
    const float* qkv_b  = (const float*)d_in[2];
    const float* proj_w = (const float*)d_in[3];
    const float* proj_b = (const float*)d_in[4];
    float* out = (float*)d_out;
    (void)in_sizes; (void)n_in; (void)out_size;

    cudaFuncSetAttribute(mma_gemm<0>,
                         cudaFuncAttributeMaxDynamicSharedMemorySize, GSMEM);
    cudaFuncSetAttribute(mma_gemm<1>,
                         cudaFuncAttributeMaxDynamicSharedMemorySize, GSMEM);
    cudaFuncSetAttribute(attn_mma_kernel,
                         cudaFuncAttributeMaxDynamicSharedMemorySize, AT_SMEM);

    __half *x16, *w16, *p16, *a16;
    cudaGetSymbolAddress((void**)&x16, g_x16);
    cudaGetSymbolAddress((void**)&w16, g_w16);
    cudaGetSymbolAddress((void**)&p16, g_p16);
    cudaGetSymbolAddress((void**)&a16, g_a16);

    // 1) operand prep (convert/transpose to fp16)
    convert_f16_kernel<<<(BT_*CC/4 + 255)/256, 256>>>(x, x16, BT_*CC/4);
    transpose_f16_kernel<<<dim3(N3C/32, CC/32), dim3(32, 8)>>>(qkv_w, w16, CC, N3C);
    transpose_f16_kernel<<<dim3(CC/32, CC/32), dim3(32, 8)>>>(proj_w, p16, CC, CC);

    // 2) QKV GEMM (fp16 single-pass) -> Q/K/V fp16 [B,H,T,D]
    mma_gemm<0><<<dim3(N3C/128, BT_/128), 256, GSMEM>>>(x16, w16, qkv_b, nullptr);

    // 3) tensor-core flash attention (single-pass) -> fp16 attention output
    attn_mma_kernel<<<dim3(TT/64, BB*HH), 128, AT_SMEM>>>();

    // 4) output projection (fp16 single-pass) -> d_out
    mma_gemm<1><<<dim3(CC/128, BT_/128), 256, GSMEM>>>(a16, p16, proj_b, out);
}